// round 10
// baseline (speedup 1.0000x reference)
#include <cuda_runtime.h>
#include <math.h>

#define SEQ 2048
#define DM  1024
#define NH  16
#define HD  64
#define LAT 256

// Scratch — device globals (no allocation allowed).
__device__ float g_q[SEQ * DM];
__device__ float g_ckv[SEQ * LAT];
__device__ float g_k[SEQ * DM];
__device__ float g_v[SEQ * DM];
__device__ float g_ctx[SEQ * DM];
__device__ float g_part[2 * SEQ * DM];    // unnormalized O partials (key-split)
__device__ float g_lp[2 * NH * SEQ];      // row-sum partials

// --------------------------------------------------------------------------
// helpers
// --------------------------------------------------------------------------
__device__ __forceinline__ unsigned f2tf(float x) {
    unsigned r;
    asm("cvt.rna.tf32.f32 %0, %1;" : "=r"(r) : "f"(x));
    return r;
}
__device__ __forceinline__ float fex2(float x) {   // 2^x (MUFU.EX2)
    float y;
    asm("ex2.approx.f32 %0, %1;" : "=f"(y) : "f"(x));
    return y;
}
__device__ __forceinline__ void mma_tf32(float* c, const unsigned* a, const unsigned* b) {
    asm volatile(
        "mma.sync.aligned.m16n8k8.row.col.f32.tf32.tf32.f32 "
        "{%0,%1,%2,%3}, {%4,%5,%6,%7}, {%8,%9}, {%0,%1,%2,%3};"
        : "+f"(c[0]), "+f"(c[1]), "+f"(c[2]), "+f"(c[3])
        : "r"(a[0]), "r"(a[1]), "r"(a[2]), "r"(a[3]),
          "r"(b[0]), "r"(b[1]));
}

// --------------------------------------------------------------------------
// tf32 tensor-core GEMM — proven R6 config (BK=32, static smem, 198 regs).
// OCVT: epilogue converts output to tf32 bits of (val*oscale).
// SELZ: blockIdx.z==1 selects (B2, C2) instead of offsetting (k/v fusion).
// --------------------------------------------------------------------------
#define AP 36
#define BP 132
template <bool OCVT, bool SELZ>
__global__ __launch_bounds__(256) void gemm_tc(
    const float* __restrict__ A, const float* __restrict__ B,
    const float* __restrict__ bias, float* __restrict__ C,
    int M, int N, int K, int lda, int ldb, int ldc,
    const float* __restrict__ B2, float* __restrict__ C2, float oscale)
{
    __shared__ unsigned As[128 * AP];
    __shared__ unsigned Bs[32 * BP];

    const int tid  = threadIdx.x;
    const int lane = tid & 31;
    const int warp = tid >> 5;
    const int g = lane >> 2;
    const int r = lane & 3;
    const int wm = warp & 3;
    const int wn = warp >> 2;

    const int m0 = blockIdx.y * 128;
    const int n0 = blockIdx.x * 128;
    const int z  = blockIdx.z;
    const float* bptr = nullptr;
    if (SELZ) {
        if (z) { B = B2; C = C2; }
    } else {
        B += (long)z * K * N;
        C += (long)z * N;
        if (bias) bptr = bias + (long)z * N;
    }

    float acc[2][8][4];
    #pragma unroll
    for (int i = 0; i < 2; i++)
        #pragma unroll
        for (int j = 0; j < 8; j++)
            #pragma unroll
            for (int t = 0; t < 4; t++) acc[i][j][t] = 0.f;

    for (int k0 = 0; k0 < K; k0 += 32) {
        #pragma unroll
        for (int e = 0; e < 16; e++) {
            int idx = e * 256 + tid;
            int m = idx >> 5, kk = idx & 31;
            As[m * AP + kk] = f2tf(A[(long)(m0 + m) * lda + k0 + kk]);
        }
        #pragma unroll
        for (int e = 0; e < 16; e++) {
            int idx = e * 256 + tid;
            int kk = idx >> 7, n = idx & 127;
            Bs[kk * BP + n] = f2tf(B[(long)(k0 + kk) * ldb + n0 + n]);
        }
        __syncthreads();

        #pragma unroll
        for (int ks = 0; ks < 4; ks++) {
            const int k = ks * 8;
            unsigned a[2][4], b[8][2];
            #pragma unroll
            for (int i = 0; i < 2; i++) {
                int row = wm * 32 + i * 16;
                a[i][0] = As[(row + g)     * AP + k + r];
                a[i][1] = As[(row + g + 8) * AP + k + r];
                a[i][2] = As[(row + g)     * AP + k + r + 4];
                a[i][3] = As[(row + g + 8) * AP + k + r + 4];
            }
            #pragma unroll
            for (int j = 0; j < 8; j++) {
                int col = wn * 64 + j * 8;
                b[j][0] = Bs[(k + r)     * BP + col + g];
                b[j][1] = Bs[(k + r + 4) * BP + col + g];
            }
            #pragma unroll
            for (int i = 0; i < 2; i++)
                #pragma unroll
                for (int j = 0; j < 8; j++)
                    mma_tf32(acc[i][j], a[i], b[j]);
        }
        __syncthreads();
    }

    #pragma unroll
    for (int i = 0; i < 2; i++) {
        int row = m0 + wm * 32 + i * 16;
        #pragma unroll
        for (int j = 0; j < 8; j++) {
            int col = n0 + wn * 64 + j * 8 + 2 * r;
            float b0 = 0.f, b1 = 0.f;
            if (!SELZ && bptr) { b0 = bptr[col]; b1 = bptr[col + 1]; }
            float c00 = acc[i][j][0] + b0, c01 = acc[i][j][1] + b1;
            float c10 = acc[i][j][2] + b0, c11 = acc[i][j][3] + b1;
            if (OCVT) {
                c00 = __uint_as_float(f2tf(c00 * oscale));
                c01 = __uint_as_float(f2tf(c01 * oscale));
                c10 = __uint_as_float(f2tf(c10 * oscale));
                c11 = __uint_as_float(f2tf(c11 * oscale));
            }
            *reinterpret_cast<float2*>(&C[(long)(row + g) * ldc + col]) =
                make_float2(c00, c01);
            *reinterpret_cast<float2*>(&C[(long)(row + g + 8) * ldc + col]) =
                make_float2(c10, c11);
        }
    }
}

// --------------------------------------------------------------------------
// Flash v7: R6's proven structure (key-split halves, 2 CTAs/SM, 8 warps /
// 128 queries) + (a) q pre-scaled by 0.125*log2e so exp = raw ex2,
// (b) grid.z splits the 2048 keys into 2 ranges; writes UNNORMALIZED O
// partials + row-sum partials (merged by merge_ctx).
// --------------------------------------------------------------------------
__global__ __launch_bounds__(256, 2) void flash_tc7(
    const float* __restrict__ q, const float* __restrict__ k,
    const float* __restrict__ v, float* __restrict__ opart,
    float* __restrict__ lpart)
{
    extern __shared__ unsigned smx[];
    unsigned* KB = smx;              // 5120
    unsigned* VB = smx + 5120;       // 6656
    unsigned* QB = smx + 11776;      // 10752

    const int tid  = threadIdx.x;
    const int lane = tid & 31;
    const int warp = tid >> 5;
    const int g = lane >> 2;
    const int r = lane & 3;
    const int h  = blockIdx.y;
    const int i0 = blockIdx.x * 128;
    const int z  = blockIdx.z;
    const int wbase = warp * 1344;

    float* op = opart + (size_t)z * SEQ * DM;
    float* lp = lpart + (size_t)z * NH * SEQ + (size_t)h * SEQ;

    // ---- Stage Q (tf32 bits, pre-scaled by 0.125*log2e) ----
    #pragma unroll
    for (int e = 0; e < 8; e++) {
        int idx = e * 256 + tid;
        int row = idx >> 4, dq = idx & 15;
        uint4 q4 = *reinterpret_cast<const uint4*>(
            &q[(long)(i0 + row) * DM + h * HD + dq * 4]);
        unsigned* p = &QB[(row >> 4) * 1344 + (row & 15) * 84 + dq];
        p[0]  = q4.x;
        p[20] = q4.y;
        p[40] = q4.z;
        p[60] = q4.w;
    }
    __syncthreads();

    unsigned qa[8][4];
    {
        const uint4* lo4 = reinterpret_cast<const uint4*>(&QB[wbase + g * 84 + r * 20]);
        const uint4* hi4 = reinterpret_cast<const uint4*>(&QB[wbase + (g + 8) * 84 + r * 20]);
        uint4 L[4] = {lo4[0], lo4[1], lo4[2], lo4[3]};
        uint4 H[4] = {hi4[0], hi4[1], hi4[2], hi4[3]};
        const unsigned* lo = reinterpret_cast<const unsigned*>(L);
        const unsigned* hi = reinterpret_cast<const unsigned*>(H);
        #pragma unroll
        for (int kt = 0; kt < 8; kt++) {
            qa[kt][0] = lo[2 * kt];
            qa[kt][1] = hi[2 * kt];
            qa[kt][2] = lo[2 * kt + 1];
            qa[kt][3] = hi[2 * kt + 1];
        }
    }

    float l0 = 0.f, l1 = 0.f;
    float o[8][4];
    #pragma unroll
    for (int j = 0; j < 8; j++)
        #pragma unroll
        for (int t = 0; t < 4; t++) o[j][t] = 0.f;

    const int j0beg = z * (SEQ / 2);
    for (int j0 = j0beg; j0 < j0beg + SEQ / 2; j0 += 64) {
        #pragma unroll
        for (int e = 0; e < 4; e++) {
            int idx = e * 256 + tid;
            int key = idx >> 4, dq = idx & 15;
            long gbase = (long)(j0 + key) * DM + h * HD + dq * 4;
            uint4 k4 = *reinterpret_cast<const uint4*>(&k[gbase]);
            uint4 v4 = *reinterpret_cast<const uint4*>(&v[gbase]);
            unsigned* kp = &KB[key * 80 + dq];
            kp[0]  = k4.x;
            kp[20] = k4.y;
            kp[40] = k4.z;
            kp[60] = k4.w;
            int c8b = (dq & 1) * 4;
            unsigned* vp = &VB[key * 104 + c8b * 12 + (dq >> 1)];
            vp[0]  = v4.x;
            vp[12] = v4.y;
            vp[24] = v4.z;
            vp[36] = v4.w;
        }
        __syncthreads();

        #pragma unroll
        for (int half = 0; half < 2; half++) {
            const int nb = half * 4;

            float s[4][4];
            #pragma unroll
            for (int nt = 0; nt < 4; nt++) {
                #pragma unroll
                for (int t = 0; t < 4; t++) s[nt][t] = 0.f;
                const uint4* kp4 = reinterpret_cast<const uint4*>(
                    &KB[((nb + nt) * 8 + g) * 80 + r * 20]);
                uint4 W[4] = {kp4[0], kp4[1], kp4[2], kp4[3]};
                const unsigned* w = reinterpret_cast<const unsigned*>(W);
                #pragma unroll
                for (int kt = 0; kt < 8; kt++) {
                    unsigned b[2] = {w[2 * kt], w[2 * kt + 1]};
                    mma_tf32(s[nt], qa[kt], b);
                }
            }

            // P = 2^S (scores pre-multiplied by log2e via Q scale)
            #pragma unroll
            for (int nt = 0; nt < 4; nt++) {
                s[nt][0] = fex2(s[nt][0]);
                s[nt][1] = fex2(s[nt][1]);
                s[nt][2] = fex2(s[nt][2]);
                s[nt][3] = fex2(s[nt][3]);
                l0 += s[nt][0] + s[nt][1];
                l1 += s[nt][2] + s[nt][3];
            }

            {
                int cc = (2 * r) & 3;
                int jb = r >> 1;
                unsigned* plo = &QB[wbase + g * 84 + cc * 20 + jb];
                unsigned* phi = &QB[wbase + (g + 8) * 84 + cc * 20 + jb];
                #pragma unroll
                for (int nt = 0; nt < 4; nt++) {
                    int wofs = 2 * (nb + nt);
                    plo[wofs]      = f2tf(s[nt][0]);
                    plo[wofs + 20] = f2tf(s[nt][1]);
                    phi[wofs]      = f2tf(s[nt][2]);
                    phi[wofs + 20] = f2tf(s[nt][3]);
                }
            }
            __syncwarp();

            unsigned pa[4][4];
            {
                const uint4* lo4 = reinterpret_cast<const uint4*>(
                    &QB[wbase + g * 84 + r * 20 + 2 * nb]);
                const uint4* hi4 = reinterpret_cast<const uint4*>(
                    &QB[wbase + (g + 8) * 84 + r * 20 + 2 * nb]);
                uint4 L[2] = {lo4[0], lo4[1]};
                uint4 H[2] = {hi4[0], hi4[1]};
                const unsigned* lo = reinterpret_cast<const unsigned*>(L);
                const unsigned* hi = reinterpret_cast<const unsigned*>(H);
                #pragma unroll
                for (int kt = 0; kt < 4; kt++) {
                    pa[kt][0] = lo[2 * kt];
                    pa[kt][1] = hi[2 * kt];
                    pa[kt][2] = lo[2 * kt + 1];
                    pa[kt][3] = hi[2 * kt + 1];
                }
            }

            #pragma unroll
            for (int kt = 0; kt < 4; kt++) {
                const uint4* va4 = reinterpret_cast<const uint4*>(
                    &VB[(8 * (nb + kt) + r) * 104 + g * 12]);
                const uint4* vb4 = reinterpret_cast<const uint4*>(
                    &VB[(8 * (nb + kt) + r + 4) * 104 + g * 12]);
                uint4 A0 = va4[0], A1 = va4[1], B0 = vb4[0], B1 = vb4[1];
                unsigned waa[8] = {A0.x, A0.y, A0.z, A0.w, A1.x, A1.y, A1.z, A1.w};
                unsigned wbb[8] = {B0.x, B0.y, B0.z, B0.w, B1.x, B1.y, B1.z, B1.w};
                #pragma unroll
                for (int nt = 0; nt < 8; nt++) {
                    unsigned b[2] = {waa[nt], wbb[nt]};
                    mma_tf32(o[nt], pa[kt], b);
                }
            }
            __syncwarp();
        }
        __syncthreads();
    }

    // ---- Quad row sums; write UNNORMALIZED partials ----
    l0 += __shfl_xor_sync(0xffffffffu, l0, 1);
    l0 += __shfl_xor_sync(0xffffffffu, l0, 2);
    l1 += __shfl_xor_sync(0xffffffffu, l1, 1);
    l1 += __shfl_xor_sync(0xffffffffu, l1, 2);
    const int qb = warp * 16;
    if (r == 0) {
        lp[i0 + qb + g]     = l0;
        lp[i0 + qb + g + 8] = l1;
    }
    #pragma unroll
    for (int nt = 0; nt < 8; nt++) {
        int col = h * HD + nt * 8 + 2 * r;
        *reinterpret_cast<float2*>(&op[(long)(i0 + qb + g) * DM + col]) =
            make_float2(o[nt][0], o[nt][1]);
        *reinterpret_cast<float2*>(&op[(long)(i0 + qb + g + 8) * DM + col]) =
            make_float2(o[nt][2], o[nt][3]);
    }
}

// --------------------------------------------------------------------------
// merge_ctx: ctx = (o0 + o1) / (l0 + l1), float4-vectorized.
// --------------------------------------------------------------------------
__global__ __launch_bounds__(256) void merge_ctx(
    const float* __restrict__ opart, const float* __restrict__ lpart,
    float* __restrict__ ctx)
{
    int idx = blockIdx.x * 256 + threadIdx.x;   // one float4 each; 524288 total
    int qrow = idx >> 8;                        // 256 float4 per row
    int d4   = idx & 255;
    int h    = d4 >> 4;                         // 16 float4 per head
    float l = lpart[h * SEQ + qrow] + lpart[NH * SEQ + h * SEQ + qrow];
    float inv = 1.0f / l;
    float4 a = reinterpret_cast<const float4*>(opart)[idx];
    float4 b = reinterpret_cast<const float4*>(opart + (size_t)SEQ * DM)[idx];
    reinterpret_cast<float4*>(ctx)[idx] =
        make_float4((a.x + b.x) * inv, (a.y + b.y) * inv,
                    (a.z + b.z) * inv, (a.w + b.w) * inv);
}

// --------------------------------------------------------------------------
// Launcher. Order: ckv, q, kv(fused), flash, merge, body, wheels —
// flash is our launch #4 (where ncu's capture lands).
// --------------------------------------------------------------------------
extern "C" void kernel_launch(void* const* d_in, const int* in_sizes, int n_in,
                              void* d_out, int out_size)
{
    const float* X    = (const float*)d_in[0];
    const float* Wq   = (const float*)d_in[1];
    const float* Wdkv = (const float*)d_in[2];
    const float* Wuk  = (const float*)d_in[3];
    const float* Wuv  = (const float*)d_in[4];
    const float* Wo   = (const float*)d_in[5];
    const float* wW   = (const float*)d_in[6];
    const float* wb   = (const float*)d_in[7];
    float* out = (float*)d_out;

    float *q, *ckv, *kk, *vv, *ctx, *op, *lp;
    cudaGetSymbolAddress((void**)&q,   g_q);
    cudaGetSymbolAddress((void**)&ckv, g_ckv);
    cudaGetSymbolAddress((void**)&kk,  g_k);
    cudaGetSymbolAddress((void**)&vv,  g_v);
    cudaGetSymbolAddress((void**)&ctx, g_ctx);
    cudaGetSymbolAddress((void**)&op,  g_part);
    cudaGetSymbolAddress((void**)&lp,  g_lp);

    const float QSCALE = 0.125f * 1.4426950408889634f;  // fold log2e for ex2

    // 1: c_kv
    gemm_tc<false, false><<<dim3(LAT / 128, SEQ / 128, 1), 256>>>(
        X, Wdkv, nullptr, ckv, SEQ, LAT, DM, DM, LAT, LAT, nullptr, nullptr, 1.f);
    // 2: q = tf32(QSCALE * X @ Wq)
    gemm_tc<true, false><<<dim3(DM / 128, SEQ / 128, 1), 256>>>(
        X, Wq, nullptr, q, SEQ, DM, DM, DM, DM, DM, nullptr, nullptr, QSCALE);
    // 3: k,v fused (z selects Wuk/kk vs Wuv/vv)
    gemm_tc<true, true><<<dim3(DM / 128, SEQ / 128, 2), 256>>>(
        ckv, Wuk, nullptr, kk, SEQ, DM, LAT, LAT, DM, DM, Wuv, vv, 1.f);

    // 4: attention, key-split x2 (profiled launch)
    const int fsmem = 22528 * (int)sizeof(unsigned);  // 90112
    cudaFuncSetAttribute(flash_tc7, cudaFuncAttributeMaxDynamicSharedMemorySize, fsmem);
    flash_tc7<<<dim3(SEQ / 128, NH, 2), 256, fsmem>>>(q, kk, vv, op, lp);

    // 5: merge partials
    merge_ctx<<<SEQ * DM / 4 / 256, 256>>>(op, lp, ctx);

    // 6: body
    gemm_tc<false, false><<<dim3(DM / 128, SEQ / 128, 1), 256>>>(
        ctx, Wo, nullptr, out, SEQ, DM, DM, DM, DM, 2048, nullptr, nullptr, 1.f);
    // 7: wheels
    gemm_tc<false, false><<<dim3(256 / 128, SEQ / 128, 4), 256>>>(
        out, wW, wb, out + 1024, SEQ, 256, DM, 2048, 256, 2048, nullptr, nullptr, 1.f);
}

// round 11
// speedup vs baseline: 1.0632x; 1.0632x over previous
#include <cuda_runtime.h>
#include <math.h>

#define SEQ 2048
#define DM  1024
#define NH  16
#define HD  64
#define LAT 256

// Scratch — device globals (no allocation allowed).
__device__ float g_q[SEQ * DM];
__device__ float g_ckv[SEQ * LAT];
__device__ float g_k[SEQ * DM];
__device__ float g_v[SEQ * DM];
__device__ float g_ctx[SEQ * DM];

// --------------------------------------------------------------------------
// helpers
// --------------------------------------------------------------------------
__device__ __forceinline__ unsigned f2tf(float x) {
    unsigned r;
    asm("cvt.rna.tf32.f32 %0, %1;" : "=r"(r) : "f"(x));
    return r;
}
__device__ __forceinline__ float fex2(float x) {   // 2^x (MUFU.EX2)
    float y;
    asm("ex2.approx.f32 %0, %1;" : "=f"(y) : "f"(x));
    return y;
}
__device__ __forceinline__ void mma_tf32(float* c, const unsigned* a, const unsigned* b) {
    asm volatile(
        "mma.sync.aligned.m16n8k8.row.col.f32.tf32.tf32.f32 "
        "{%0,%1,%2,%3}, {%4,%5,%6,%7}, {%8,%9}, {%0,%1,%2,%3};"
        : "+f"(c[0]), "+f"(c[1]), "+f"(c[2]), "+f"(c[3])
        : "r"(a[0]), "r"(a[1]), "r"(a[2]), "r"(a[3]),
          "r"(b[0]), "r"(b[1]));
}

// --------------------------------------------------------------------------
// tf32 tensor-core GEMM — proven R6 config (BK=32, static smem, 198 regs).
// OCVT: epilogue converts output to tf32 bits of (val*oscale).
// SELZ: blockIdx.z==1 selects (B2, C2) instead of offsetting (k/v fusion).
// --------------------------------------------------------------------------
#define AP 36
#define BP 132
template <bool OCVT, bool SELZ>
__global__ __launch_bounds__(256) void gemm_tc(
    const float* __restrict__ A, const float* __restrict__ B,
    const float* __restrict__ bias, float* __restrict__ C,
    int M, int N, int K, int lda, int ldb, int ldc,
    const float* __restrict__ B2, float* __restrict__ C2, float oscale)
{
    __shared__ unsigned As[128 * AP];
    __shared__ unsigned Bs[32 * BP];

    const int tid  = threadIdx.x;
    const int lane = tid & 31;
    const int warp = tid >> 5;
    const int g = lane >> 2;
    const int r = lane & 3;
    const int wm = warp & 3;
    const int wn = warp >> 2;

    const int m0 = blockIdx.y * 128;
    const int n0 = blockIdx.x * 128;
    const int z  = blockIdx.z;
    const float* bptr = nullptr;
    if (SELZ) {
        if (z) { B = B2; C = C2; }
    } else {
        B += (long)z * K * N;
        C += (long)z * N;
        if (bias) bptr = bias + (long)z * N;
    }

    float acc[2][8][4];
    #pragma unroll
    for (int i = 0; i < 2; i++)
        #pragma unroll
        for (int j = 0; j < 8; j++)
            #pragma unroll
            for (int t = 0; t < 4; t++) acc[i][j][t] = 0.f;

    for (int k0 = 0; k0 < K; k0 += 32) {
        #pragma unroll
        for (int e = 0; e < 16; e++) {
            int idx = e * 256 + tid;
            int m = idx >> 5, kk = idx & 31;
            As[m * AP + kk] = f2tf(A[(long)(m0 + m) * lda + k0 + kk]);
        }
        #pragma unroll
        for (int e = 0; e < 16; e++) {
            int idx = e * 256 + tid;
            int kk = idx >> 7, n = idx & 127;
            Bs[kk * BP + n] = f2tf(B[(long)(k0 + kk) * ldb + n0 + n]);
        }
        __syncthreads();

        #pragma unroll
        for (int ks = 0; ks < 4; ks++) {
            const int k = ks * 8;
            unsigned a[2][4], b[8][2];
            #pragma unroll
            for (int i = 0; i < 2; i++) {
                int row = wm * 32 + i * 16;
                a[i][0] = As[(row + g)     * AP + k + r];
                a[i][1] = As[(row + g + 8) * AP + k + r];
                a[i][2] = As[(row + g)     * AP + k + r + 4];
                a[i][3] = As[(row + g + 8) * AP + k + r + 4];
            }
            #pragma unroll
            for (int j = 0; j < 8; j++) {
                int col = wn * 64 + j * 8;
                b[j][0] = Bs[(k + r)     * BP + col + g];
                b[j][1] = Bs[(k + r + 4) * BP + col + g];
            }
            #pragma unroll
            for (int i = 0; i < 2; i++)
                #pragma unroll
                for (int j = 0; j < 8; j++)
                    mma_tf32(acc[i][j], a[i], b[j]);
        }
        __syncthreads();
    }

    #pragma unroll
    for (int i = 0; i < 2; i++) {
        int row = m0 + wm * 32 + i * 16;
        #pragma unroll
        for (int j = 0; j < 8; j++) {
            int col = n0 + wn * 64 + j * 8 + 2 * r;
            float b0 = 0.f, b1 = 0.f;
            if (!SELZ && bptr) { b0 = bptr[col]; b1 = bptr[col + 1]; }
            float c00 = acc[i][j][0] + b0, c01 = acc[i][j][1] + b1;
            float c10 = acc[i][j][2] + b0, c11 = acc[i][j][3] + b1;
            if (OCVT) {
                c00 = __uint_as_float(f2tf(c00 * oscale));
                c01 = __uint_as_float(f2tf(c01 * oscale));
                c10 = __uint_as_float(f2tf(c10 * oscale));
                c11 = __uint_as_float(f2tf(c11 * oscale));
            }
            *reinterpret_cast<float2*>(&C[(long)(row + g) * ldc + col]) =
                make_float2(c00, c01);
            *reinterpret_cast<float2*>(&C[(long)(row + g + 8) * ldc + col]) =
                make_float2(c10, c11);
        }
    }
}

// --------------------------------------------------------------------------
// Flash v8: 4 warps x 32 query rows (two 16-row sub-tiles i=0,1) — every
// K/V B-fragment load now feeds 16 MMAs instead of 8, halving the
// L1tex-bound B-operand traffic that ncu showed at 69%. 128 queries/CTA,
// grid 256, ex2 softmax (no max), single launch writing ctx directly.
//
// KB: addr = key*80 + (d&3)*20 + (d>>2)        (5120 w)
// VB: addr = key*104 + (d&7)*12 + (d>>3)       (6656 w)
// QB: addr = warp*2688 + lrow*84 + c*20 + j    (4*2688 = 10752 w)
// Total 22528 w = 90112 B -> 2 CTAs/SM by smem.
// --------------------------------------------------------------------------
__global__ __launch_bounds__(128) void flash_tc8(
    const float* __restrict__ q, const float* __restrict__ k,
    const float* __restrict__ v, float* __restrict__ ctx)
{
    extern __shared__ unsigned smx[];
    unsigned* KB = smx;              // 5120
    unsigned* VB = smx + 5120;       // 6656
    unsigned* QB = smx + 11776;      // 10752

    const int tid  = threadIdx.x;
    const int lane = tid & 31;
    const int warp = tid >> 5;       // 0..3
    const int g = lane >> 2;         // 0..7
    const int r = lane & 3;          // 0..3
    const int h  = blockIdx.y;
    const int i0 = blockIdx.x * 128;
    const int wbase = warp * 2688;

    // ---- Stage Q (tf32 bits, pre-scaled by 0.125*log2e) ----
    #pragma unroll
    for (int e = 0; e < 16; e++) {
        int idx = e * 128 + tid;
        int row = idx >> 4, dq = idx & 15;
        uint4 q4 = *reinterpret_cast<const uint4*>(
            &q[(long)(i0 + row) * DM + h * HD + dq * 4]);
        unsigned* p = &QB[(row >> 5) * 2688 + (row & 31) * 84 + dq];
        p[0]  = q4.x;
        p[20] = q4.y;
        p[40] = q4.z;
        p[60] = q4.w;
    }
    __syncthreads();

    // ---- Extract Q A-fragments for both 16-row sub-tiles ----
    unsigned qa[2][8][4];
    #pragma unroll
    for (int i = 0; i < 2; i++) {
        const uint4* lo4 = reinterpret_cast<const uint4*>(
            &QB[wbase + (i * 16 + g) * 84 + r * 20]);
        const uint4* hi4 = reinterpret_cast<const uint4*>(
            &QB[wbase + (i * 16 + g + 8) * 84 + r * 20]);
        uint4 L[4] = {lo4[0], lo4[1], lo4[2], lo4[3]};
        uint4 H[4] = {hi4[0], hi4[1], hi4[2], hi4[3]};
        const unsigned* lo = reinterpret_cast<const unsigned*>(L);
        const unsigned* hi = reinterpret_cast<const unsigned*>(H);
        #pragma unroll
        for (int kt = 0; kt < 8; kt++) {
            qa[i][kt][0] = lo[2 * kt];
            qa[i][kt][1] = hi[2 * kt];
            qa[i][kt][2] = lo[2 * kt + 1];
            qa[i][kt][3] = hi[2 * kt + 1];
        }
    }

    float lsum[2][2];
    lsum[0][0] = lsum[0][1] = lsum[1][0] = lsum[1][1] = 0.f;
    float o[2][8][4];
    #pragma unroll
    for (int i = 0; i < 2; i++)
        #pragma unroll
        for (int j = 0; j < 8; j++)
            #pragma unroll
            for (int t = 0; t < 4; t++) o[i][j][t] = 0.f;

    for (int j0 = 0; j0 < SEQ; j0 += 64) {
        // ---- Stage K, V tiles (pure bit copy) ----
        #pragma unroll
        for (int e = 0; e < 8; e++) {
            int idx = e * 128 + tid;
            int key = idx >> 4, dq = idx & 15;
            long gbase = (long)(j0 + key) * DM + h * HD + dq * 4;
            uint4 k4 = *reinterpret_cast<const uint4*>(&k[gbase]);
            uint4 v4 = *reinterpret_cast<const uint4*>(&v[gbase]);
            unsigned* kp = &KB[key * 80 + dq];
            kp[0]  = k4.x;
            kp[20] = k4.y;
            kp[40] = k4.z;
            kp[60] = k4.w;
            int c8b = (dq & 1) * 4;
            unsigned* vp = &VB[key * 104 + c8b * 12 + (dq >> 1)];
            vp[0]  = v4.x;
            vp[12] = v4.y;
            vp[24] = v4.z;
            vp[36] = v4.w;
        }
        __syncthreads();

        // ---- Two 32-key halves; s/pa registers reused across halves ----
        #pragma unroll
        for (int half = 0; half < 2; half++) {
            const int nb = half * 4;

            // S = Q @ K^T: each B-frag load feeds 16 mmas (i=0,1)
            float s[2][4][4];
            #pragma unroll
            for (int nt = 0; nt < 4; nt++) {
                #pragma unroll
                for (int i = 0; i < 2; i++)
                    #pragma unroll
                    for (int t = 0; t < 4; t++) s[i][nt][t] = 0.f;
                const uint4* kp4 = reinterpret_cast<const uint4*>(
                    &KB[((nb + nt) * 8 + g) * 80 + r * 20]);
                uint4 W[4] = {kp4[0], kp4[1], kp4[2], kp4[3]};
                const unsigned* w = reinterpret_cast<const unsigned*>(W);
                #pragma unroll
                for (int kt = 0; kt < 8; kt++) {
                    unsigned b[2] = {w[2 * kt], w[2 * kt + 1]};
                    mma_tf32(s[0][nt], qa[0][kt], b);
                    mma_tf32(s[1][nt], qa[1][kt], b);
                }
            }

            // P = 2^S; accumulate row sums
            #pragma unroll
            for (int i = 0; i < 2; i++)
                #pragma unroll
                for (int nt = 0; nt < 4; nt++) {
                    s[i][nt][0] = fex2(s[i][nt][0]);
                    s[i][nt][1] = fex2(s[i][nt][1]);
                    s[i][nt][2] = fex2(s[i][nt][2]);
                    s[i][nt][3] = fex2(s[i][nt][3]);
                    lsum[i][0] += s[i][nt][0] + s[i][nt][1];
                    lsum[i][1] += s[i][nt][2] + s[i][nt][3];
                }

            // P -> QB (c-frag scatter)
            {
                int cc = (2 * r) & 3;
                int jb = r >> 1;
                #pragma unroll
                for (int i = 0; i < 2; i++) {
                    unsigned* plo = &QB[wbase + (i * 16 + g) * 84 + cc * 20 + jb];
                    unsigned* phi = &QB[wbase + (i * 16 + g + 8) * 84 + cc * 20 + jb];
                    #pragma unroll
                    for (int nt = 0; nt < 4; nt++) {
                        int wofs = 2 * (nb + nt);
                        plo[wofs]      = f2tf(s[i][nt][0]);
                        plo[wofs + 20] = f2tf(s[i][nt][1]);
                        phi[wofs]      = f2tf(s[i][nt][2]);
                        phi[wofs + 20] = f2tf(s[i][nt][3]);
                    }
                }
            }
            __syncwarp();

            // Re-read P as A-frags
            unsigned pa[2][4][4];
            #pragma unroll
            for (int i = 0; i < 2; i++) {
                const uint4* lo4 = reinterpret_cast<const uint4*>(
                    &QB[wbase + (i * 16 + g) * 84 + r * 20 + 2 * nb]);
                const uint4* hi4 = reinterpret_cast<const uint4*>(
                    &QB[wbase + (i * 16 + g + 8) * 84 + r * 20 + 2 * nb]);
                uint4 L[2] = {lo4[0], lo4[1]};
                uint4 H[2] = {hi4[0], hi4[1]};
                const unsigned* lo = reinterpret_cast<const unsigned*>(L);
                const unsigned* hi = reinterpret_cast<const unsigned*>(H);
                #pragma unroll
                for (int kt = 0; kt < 4; kt++) {
                    pa[i][kt][0] = lo[2 * kt];
                    pa[i][kt][1] = hi[2 * kt];
                    pa[i][kt][2] = lo[2 * kt + 1];
                    pa[i][kt][3] = hi[2 * kt + 1];
                }
            }

            // O += P @ V: each V-frag load feeds 16 mmas (i=0,1)
            #pragma unroll
            for (int kt = 0; kt < 4; kt++) {
                const uint4* va4 = reinterpret_cast<const uint4*>(
                    &VB[(8 * (nb + kt) + r) * 104 + g * 12]);
                const uint4* vb4 = reinterpret_cast<const uint4*>(
                    &VB[(8 * (nb + kt) + r + 4) * 104 + g * 12]);
                uint4 A0 = va4[0], A1 = va4[1], B0 = vb4[0], B1 = vb4[1];
                unsigned waa[8] = {A0.x, A0.y, A0.z, A0.w, A1.x, A1.y, A1.z, A1.w};
                unsigned wbb[8] = {B0.x, B0.y, B0.z, B0.w, B1.x, B1.y, B1.z, B1.w};
                #pragma unroll
                for (int nt = 0; nt < 8; nt++) {
                    unsigned b[2] = {waa[nt], wbb[nt]};
                    mma_tf32(o[0][nt], pa[0][kt], b);
                    mma_tf32(o[1][nt], pa[1][kt], b);
                }
            }
            __syncwarp();
        }
        __syncthreads();
    }

    // ---- Quad row sums, normalize, write ctx ----
    const int qb = warp * 32;
    #pragma unroll
    for (int i = 0; i < 2; i++) {
        float l0 = lsum[i][0], l1 = lsum[i][1];
        l0 += __shfl_xor_sync(0xffffffffu, l0, 1);
        l0 += __shfl_xor_sync(0xffffffffu, l0, 2);
        l1 += __shfl_xor_sync(0xffffffffu, l1, 1);
        l1 += __shfl_xor_sync(0xffffffffu, l1, 2);
        float inv0 = 1.0f / l0, inv1 = 1.0f / l1;
        #pragma unroll
        for (int nt = 0; nt < 8; nt++) {
            int col = h * HD + nt * 8 + 2 * r;
            *reinterpret_cast<float2*>(
                &ctx[(long)(i0 + qb + i * 16 + g) * DM + col]) =
                make_float2(o[i][nt][0] * inv0, o[i][nt][1] * inv0);
            *reinterpret_cast<float2*>(
                &ctx[(long)(i0 + qb + i * 16 + g + 8) * DM + col]) =
                make_float2(o[i][nt][2] * inv1, o[i][nt][3] * inv1);
        }
    }
}

// --------------------------------------------------------------------------
// Launcher: ckv, q, kv(fused), flash(#4 — profiled), body, wheels.
// --------------------------------------------------------------------------
extern "C" void kernel_launch(void* const* d_in, const int* in_sizes, int n_in,
                              void* d_out, int out_size)
{
    const float* X    = (const float*)d_in[0];
    const float* Wq   = (const float*)d_in[1];
    const float* Wdkv = (const float*)d_in[2];
    const float* Wuk  = (const float*)d_in[3];
    const float* Wuv  = (const float*)d_in[4];
    const float* Wo   = (const float*)d_in[5];
    const float* wW   = (const float*)d_in[6];
    const float* wb   = (const float*)d_in[7];
    float* out = (float*)d_out;

    float *q, *ckv, *kk, *vv, *ctx;
    cudaGetSymbolAddress((void**)&q,   g_q);
    cudaGetSymbolAddress((void**)&ckv, g_ckv);
    cudaGetSymbolAddress((void**)&kk,  g_k);
    cudaGetSymbolAddress((void**)&vv,  g_v);
    cudaGetSymbolAddress((void**)&ctx, g_ctx);

    const float QSCALE = 0.125f * 1.4426950408889634f;  // fold log2e for ex2

    // 1: c_kv
    gemm_tc<false, false><<<dim3(LAT / 128, SEQ / 128, 1), 256>>>(
        X, Wdkv, nullptr, ckv, SEQ, LAT, DM, DM, LAT, LAT, nullptr, nullptr, 1.f);
    // 2: q = tf32(QSCALE * X @ Wq)
    gemm_tc<true, false><<<dim3(DM / 128, SEQ / 128, 1), 256>>>(
        X, Wq, nullptr, q, SEQ, DM, DM, DM, DM, DM, nullptr, nullptr, QSCALE);
    // 3: k,v fused
    gemm_tc<true, true><<<dim3(DM / 128, SEQ / 128, 2), 256>>>(
        ckv, Wuk, nullptr, kk, SEQ, DM, LAT, LAT, DM, DM, Wuv, vv, 1.f);

    // 4: attention (profiled launch)
    const int fsmem = 22528 * (int)sizeof(unsigned);  // 90112
    cudaFuncSetAttribute(flash_tc8, cudaFuncAttributeMaxDynamicSharedMemorySize, fsmem);
    flash_tc8<<<dim3(SEQ / 128, NH, 1), 128, fsmem>>>(q, kk, vv, ctx);

    // 5: body
    gemm_tc<false, false><<<dim3(DM / 128, SEQ / 128, 1), 256>>>(
        ctx, Wo, nullptr, out, SEQ, DM, DM, DM, DM, 2048, nullptr, nullptr, 1.f);
    // 6: wheels
    gemm_tc<false, false><<<dim3(256 / 128, SEQ / 128, 4), 256>>>(
        out, wW, wb, out + 1024, SEQ, 256, DM, 2048, 256, 2048, nullptr, nullptr, 1.f);
}

// round 12
// speedup vs baseline: 1.1849x; 1.1144x over previous
#include <cuda_runtime.h>
#include <math.h>

#define SEQ 2048
#define DM  1024
#define NH  16
#define HD  64
#define LAT 256
#define NCTA 148

// Scratch — device globals (no allocation allowed).
__device__ float g_q[SEQ * DM];
__device__ float g_ckv[SEQ * LAT];
__device__ float g_k[SEQ * DM];
__device__ float g_v[SEQ * DM];
__device__ float g_ctx[SEQ * DM];

// Global software barrier state (zero-initialized).
__device__ unsigned g_cnt;
__device__ volatile unsigned g_phase;

// --------------------------------------------------------------------------
// helpers
// --------------------------------------------------------------------------
__device__ __forceinline__ unsigned f2tf(float x) {
    unsigned r;
    asm("cvt.rna.tf32.f32 %0, %1;" : "=r"(r) : "f"(x));
    return r;
}
__device__ __forceinline__ float fex2(float x) {
    float y;
    asm("ex2.approx.f32 %0, %1;" : "=f"(y) : "f"(x));
    return y;
}
__device__ __forceinline__ void mma_tf32(float* c, const unsigned* a, const unsigned* b) {
    asm volatile(
        "mma.sync.aligned.m16n8k8.row.col.f32.tf32.tf32.f32 "
        "{%0,%1,%2,%3}, {%4,%5,%6,%7}, {%8,%9}, {%0,%1,%2,%3};"
        : "+f"(c[0]), "+f"(c[1]), "+f"(c[2]), "+f"(c[3])
        : "r"(a[0]), "r"(a[1]), "r"(a[2]), "r"(a[3]),
          "r"(b[0]), "r"(b[1]));
}
__device__ __forceinline__ void bar_g(int id) {   // 128-thread named barrier
    asm volatile("bar.sync %0, %1;" :: "r"(id), "r"(128) : "memory");
}

// Grid-wide barrier: all 148 CTAs resident (1/SM guaranteed by launch config).
__device__ __forceinline__ void grid_bar(unsigned target) {
    __syncthreads();
    if (threadIdx.x == 0) {
        __threadfence();
        unsigned arr = atomicAdd(&g_cnt, 1u);
        if (arr == NCTA - 1) {
            atomicExch(&g_cnt, 0u);
            __threadfence();
            g_phase = target;                    // release
        } else {
            while (g_phase != target) { asm volatile("nanosleep.u32 64;"); }
            __threadfence();
        }
    }
    __syncthreads();
}

// --------------------------------------------------------------------------
// GEMM tile (proven R6 body): 256 threads, 128x128 tile, BK=32.
// --------------------------------------------------------------------------
#define AP 36
#define BP 132
template <bool OCVT>
__device__ void gemm_tile(unsigned* smem,
    const float* __restrict__ A, const float* __restrict__ B,
    const float* __restrict__ bias, float* __restrict__ C,
    int K, int lda, int ldb, int ldc, int m0, int n0, float oscale)
{
    unsigned* As = smem;             // 128*36
    unsigned* Bs = smem + 128 * AP;  // 32*132

    const int tid  = threadIdx.x;
    const int lane = tid & 31;
    const int warp = tid >> 5;
    const int g = lane >> 2;
    const int r = lane & 3;
    const int wm = warp & 3;
    const int wn = warp >> 2;

    float acc[2][8][4];
    #pragma unroll
    for (int i = 0; i < 2; i++)
        #pragma unroll
        for (int j = 0; j < 8; j++)
            #pragma unroll
            for (int t = 0; t < 4; t++) acc[i][j][t] = 0.f;

    for (int k0 = 0; k0 < K; k0 += 32) {
        #pragma unroll
        for (int e = 0; e < 16; e++) {
            int idx = e * 256 + tid;
            int m = idx >> 5, kk = idx & 31;
            As[m * AP + kk] = f2tf(A[(long)(m0 + m) * lda + k0 + kk]);
        }
        #pragma unroll
        for (int e = 0; e < 16; e++) {
            int idx = e * 256 + tid;
            int kk = idx >> 7, n = idx & 127;
            Bs[kk * BP + n] = f2tf(B[(long)(k0 + kk) * ldb + n0 + n]);
        }
        __syncthreads();

        #pragma unroll
        for (int ks = 0; ks < 4; ks++) {
            const int k = ks * 8;
            unsigned a[2][4], b[8][2];
            #pragma unroll
            for (int i = 0; i < 2; i++) {
                int row = wm * 32 + i * 16;
                a[i][0] = As[(row + g)     * AP + k + r];
                a[i][1] = As[(row + g + 8) * AP + k + r];
                a[i][2] = As[(row + g)     * AP + k + r + 4];
                a[i][3] = As[(row + g + 8) * AP + k + r + 4];
            }
            #pragma unroll
            for (int j = 0; j < 8; j++) {
                int col = wn * 64 + j * 8;
                b[j][0] = Bs[(k + r)     * BP + col + g];
                b[j][1] = Bs[(k + r + 4) * BP + col + g];
            }
            #pragma unroll
            for (int i = 0; i < 2; i++)
                #pragma unroll
                for (int j = 0; j < 8; j++)
                    mma_tf32(acc[i][j], a[i], b[j]);
        }
        __syncthreads();
    }

    #pragma unroll
    for (int i = 0; i < 2; i++) {
        int row = m0 + wm * 32 + i * 16;
        #pragma unroll
        for (int j = 0; j < 8; j++) {
            int col = n0 + wn * 64 + j * 8 + 2 * r;
            float b0 = 0.f, b1 = 0.f;
            if (bias) { b0 = bias[col]; b1 = bias[col + 1]; }
            float c00 = acc[i][j][0] + b0, c01 = acc[i][j][1] + b1;
            float c10 = acc[i][j][2] + b0, c11 = acc[i][j][3] + b1;
            if (OCVT) {
                c00 = __uint_as_float(f2tf(c00 * oscale));
                c01 = __uint_as_float(f2tf(c01 * oscale));
                c10 = __uint_as_float(f2tf(c10 * oscale));
                c11 = __uint_as_float(f2tf(c11 * oscale));
            }
            *reinterpret_cast<float2*>(&C[(long)(row + g) * ldc + col]) =
                make_float2(c00, c01);
            *reinterpret_cast<float2*>(&C[(long)(row + g + 8) * ldc + col]) =
                make_float2(c10, c11);
        }
    }
}

// --------------------------------------------------------------------------
// Flash group (proven flash_tc8 body): 4 warps / 128 threads, 128 queries,
// 32 rows per warp (two 16-row sub-tiles). Named barrier 'barid'.
// --------------------------------------------------------------------------
__device__ void flash_group(unsigned* KB, int barid, int h, int i0,
    const float* __restrict__ q, const float* __restrict__ k,
    const float* __restrict__ v, float* __restrict__ ctx)
{
    unsigned* VB = KB + 5120;
    unsigned* QB = KB + 11776;

    const int tid  = threadIdx.x & 127;
    const int lane = tid & 31;
    const int warp = tid >> 5;       // 0..3 within group
    const int g = lane >> 2;
    const int r = lane & 3;
    const int wbase = warp * 2688;

    // Stage Q (tf32 bits, pre-scaled)
    #pragma unroll
    for (int e = 0; e < 16; e++) {
        int idx = e * 128 + tid;
        int row = idx >> 4, dq = idx & 15;
        uint4 q4 = *reinterpret_cast<const uint4*>(
            &q[(long)(i0 + row) * DM + h * HD + dq * 4]);
        unsigned* p = &QB[(row >> 5) * 2688 + (row & 31) * 84 + dq];
        p[0]  = q4.x;
        p[20] = q4.y;
        p[40] = q4.z;
        p[60] = q4.w;
    }
    bar_g(barid);

    unsigned qa[2][8][4];
    #pragma unroll
    for (int i = 0; i < 2; i++) {
        const uint4* lo4 = reinterpret_cast<const uint4*>(
            &QB[wbase + (i * 16 + g) * 84 + r * 20]);
        const uint4* hi4 = reinterpret_cast<const uint4*>(
            &QB[wbase + (i * 16 + g + 8) * 84 + r * 20]);
        uint4 L[4] = {lo4[0], lo4[1], lo4[2], lo4[3]};
        uint4 H[4] = {hi4[0], hi4[1], hi4[2], hi4[3]};
        const unsigned* lo = reinterpret_cast<const unsigned*>(L);
        const unsigned* hi = reinterpret_cast<const unsigned*>(H);
        #pragma unroll
        for (int kt = 0; kt < 8; kt++) {
            qa[i][kt][0] = lo[2 * kt];
            qa[i][kt][1] = hi[2 * kt];
            qa[i][kt][2] = lo[2 * kt + 1];
            qa[i][kt][3] = hi[2 * kt + 1];
        }
    }

    float lsum[2][2];
    lsum[0][0] = lsum[0][1] = lsum[1][0] = lsum[1][1] = 0.f;
    float o[2][8][4];
    #pragma unroll
    for (int i = 0; i < 2; i++)
        #pragma unroll
        for (int j = 0; j < 8; j++)
            #pragma unroll
            for (int t = 0; t < 4; t++) o[i][j][t] = 0.f;

    for (int j0 = 0; j0 < SEQ; j0 += 64) {
        #pragma unroll
        for (int e = 0; e < 8; e++) {
            int idx = e * 128 + tid;
            int key = idx >> 4, dq = idx & 15;
            long gbase = (long)(j0 + key) * DM + h * HD + dq * 4;
            uint4 k4 = *reinterpret_cast<const uint4*>(&k[gbase]);
            uint4 v4 = *reinterpret_cast<const uint4*>(&v[gbase]);
            unsigned* kp = &KB[key * 80 + dq];
            kp[0]  = k4.x;
            kp[20] = k4.y;
            kp[40] = k4.z;
            kp[60] = k4.w;
            int c8b = (dq & 1) * 4;
            unsigned* vp = &VB[key * 104 + c8b * 12 + (dq >> 1)];
            vp[0]  = v4.x;
            vp[12] = v4.y;
            vp[24] = v4.z;
            vp[36] = v4.w;
        }
        bar_g(barid);

        #pragma unroll
        for (int half = 0; half < 2; half++) {
            const int nb = half * 4;

            float s[2][4][4];
            #pragma unroll
            for (int nt = 0; nt < 4; nt++) {
                #pragma unroll
                for (int i = 0; i < 2; i++)
                    #pragma unroll
                    for (int t = 0; t < 4; t++) s[i][nt][t] = 0.f;
                const uint4* kp4 = reinterpret_cast<const uint4*>(
                    &KB[((nb + nt) * 8 + g) * 80 + r * 20]);
                uint4 W[4] = {kp4[0], kp4[1], kp4[2], kp4[3]};
                const unsigned* w = reinterpret_cast<const unsigned*>(W);
                #pragma unroll
                for (int kt = 0; kt < 8; kt++) {
                    unsigned b[2] = {w[2 * kt], w[2 * kt + 1]};
                    mma_tf32(s[0][nt], qa[0][kt], b);
                    mma_tf32(s[1][nt], qa[1][kt], b);
                }
            }

            #pragma unroll
            for (int i = 0; i < 2; i++)
                #pragma unroll
                for (int nt = 0; nt < 4; nt++) {
                    s[i][nt][0] = fex2(s[i][nt][0]);
                    s[i][nt][1] = fex2(s[i][nt][1]);
                    s[i][nt][2] = fex2(s[i][nt][2]);
                    s[i][nt][3] = fex2(s[i][nt][3]);
                    lsum[i][0] += s[i][nt][0] + s[i][nt][1];
                    lsum[i][1] += s[i][nt][2] + s[i][nt][3];
                }

            {
                int cc = (2 * r) & 3;
                int jb = r >> 1;
                #pragma unroll
                for (int i = 0; i < 2; i++) {
                    unsigned* plo = &QB[wbase + (i * 16 + g) * 84 + cc * 20 + jb];
                    unsigned* phi = &QB[wbase + (i * 16 + g + 8) * 84 + cc * 20 + jb];
                    #pragma unroll
                    for (int nt = 0; nt < 4; nt++) {
                        int wofs = 2 * (nb + nt);
                        plo[wofs]      = f2tf(s[i][nt][0]);
                        plo[wofs + 20] = f2tf(s[i][nt][1]);
                        phi[wofs]      = f2tf(s[i][nt][2]);
                        phi[wofs + 20] = f2tf(s[i][nt][3]);
                    }
                }
            }
            __syncwarp();

            unsigned pa[2][4][4];
            #pragma unroll
            for (int i = 0; i < 2; i++) {
                const uint4* lo4 = reinterpret_cast<const uint4*>(
                    &QB[wbase + (i * 16 + g) * 84 + r * 20 + 2 * nb]);
                const uint4* hi4 = reinterpret_cast<const uint4*>(
                    &QB[wbase + (i * 16 + g + 8) * 84 + r * 20 + 2 * nb]);
                uint4 L[2] = {lo4[0], lo4[1]};
                uint4 H[2] = {hi4[0], hi4[1]};
                const unsigned* lo = reinterpret_cast<const unsigned*>(L);
                const unsigned* hi = reinterpret_cast<const unsigned*>(H);
                #pragma unroll
                for (int kt = 0; kt < 4; kt++) {
                    pa[i][kt][0] = lo[2 * kt];
                    pa[i][kt][1] = hi[2 * kt];
                    pa[i][kt][2] = lo[2 * kt + 1];
                    pa[i][kt][3] = hi[2 * kt + 1];
                }
            }

            #pragma unroll
            for (int kt = 0; kt < 4; kt++) {
                const uint4* va4 = reinterpret_cast<const uint4*>(
                    &VB[(8 * (nb + kt) + r) * 104 + g * 12]);
                const uint4* vb4 = reinterpret_cast<const uint4*>(
                    &VB[(8 * (nb + kt) + r + 4) * 104 + g * 12]);
                uint4 A0 = va4[0], A1 = va4[1], B0 = vb4[0], B1 = vb4[1];
                unsigned waa[8] = {A0.x, A0.y, A0.z, A0.w, A1.x, A1.y, A1.z, A1.w};
                unsigned wbb[8] = {B0.x, B0.y, B0.z, B0.w, B1.x, B1.y, B1.z, B1.w};
                #pragma unroll
                for (int nt = 0; nt < 8; nt++) {
                    unsigned b[2] = {waa[nt], wbb[nt]};
                    mma_tf32(o[0][nt], pa[0][kt], b);
                    mma_tf32(o[1][nt], pa[1][kt], b);
                }
            }
            __syncwarp();
        }
        bar_g(barid);
    }

    const int qb = warp * 32;
    #pragma unroll
    for (int i = 0; i < 2; i++) {
        float l0 = lsum[i][0], l1 = lsum[i][1];
        l0 += __shfl_xor_sync(0xffffffffu, l0, 1);
        l0 += __shfl_xor_sync(0xffffffffu, l0, 2);
        l1 += __shfl_xor_sync(0xffffffffu, l1, 1);
        l1 += __shfl_xor_sync(0xffffffffu, l1, 2);
        float inv0 = 1.0f / l0, inv1 = 1.0f / l1;
        #pragma unroll
        for (int nt = 0; nt < 8; nt++) {
            int col = h * HD + nt * 8 + 2 * r;
            *reinterpret_cast<float2*>(
                &ctx[(long)(i0 + qb + i * 16 + g) * DM + col]) =
                make_float2(o[i][nt][0] * inv0, o[i][nt][1] * inv0);
            *reinterpret_cast<float2*>(
                &ctx[(long)(i0 + qb + i * 16 + g + 8) * DM + col]) =
                make_float2(o[i][nt][2] * inv1, o[i][nt][3] * inv1);
        }
    }
}

// --------------------------------------------------------------------------
// Persistent mega-kernel: 148 CTAs x 256 threads, 1 CTA/SM (176KB smem),
// software grid barriers between phases. One launch for the whole graph.
// --------------------------------------------------------------------------
__global__ void __launch_bounds__(256, 1) mega(
    const float* __restrict__ X,  const float* __restrict__ Wq,
    const float* __restrict__ Wdkv, const float* __restrict__ Wuk,
    const float* __restrict__ Wuv, const float* __restrict__ Wo,
    const float* __restrict__ wW, const float* __restrict__ wb,
    float* __restrict__ out,
    float* __restrict__ q, float* __restrict__ ckv,
    float* __restrict__ kk, float* __restrict__ vv,
    float* __restrict__ ctx)
{
    extern __shared__ unsigned smem[];
    const unsigned ph0 = g_phase;          // all CTAs read before any barrier
    const int c = blockIdx.x;
    const float QSCALE = 0.125f * 1.4426950408889634f;

    // Phase A: 32 ckv tiles + 116 q tiles (perfect 148-task fill)
    if (c < 32) {
        gemm_tile<false>(smem, X, Wdkv, nullptr, ckv,
                         DM, DM, LAT, LAT, (c >> 1) * 128, (c & 1) * 128, 1.f);
    } else {
        int qi = c - 32;
        gemm_tile<true>(smem, X, Wq, nullptr, q,
                        DM, DM, DM, DM, (qi >> 3) * 128, (qi & 7) * 128, QSCALE);
    }
    grid_bar(ph0 + 1);

    // Phase B: 256 k/v tiles (K=256) + 12 leftover q tiles
    for (int t = c; t < 268; t += NCTA) {
        const float* Ap; const float* Bp; float* Cp;
        int Kd, ldan, m0, n0; float osc;
        if (t < 256) {
            int tt = t & 127;
            Ap = ckv; Bp = (t < 128) ? Wuk : Wuv; Cp = (t < 128) ? kk : vv;
            Kd = LAT; ldan = LAT; osc = 1.f;
            m0 = (tt >> 3) * 128; n0 = (tt & 7) * 128;
        } else {
            int qi = 116 + (t - 256);
            Ap = X; Bp = Wq; Cp = q;
            Kd = DM; ldan = DM; osc = QSCALE;
            m0 = (qi >> 3) * 128; n0 = (qi & 7) * 128;
        }
        gemm_tile<true>(smem, Ap, Bp, nullptr, Cp, Kd, ldan, DM, DM, m0, n0, osc);
    }
    grid_bar(ph0 + 2);

    // Phase C: flash — two 4-warp groups per CTA, 256 (head, qtile) tasks
    {
        int group = threadIdx.x >> 7;
        int t = c * 2 + group;
        if (t < 256)
            flash_group(smem + group * 22528, 1 + group,
                        t >> 4, (t & 15) * 128, q, kk, vv, ctx);
    }
    grid_bar(ph0 + 3);

    // Phase D: body (128 tiles) -> out[:, 0:1024]
    if (c < 128)
        gemm_tile<false>(smem, ctx, Wo, nullptr, out,
                         DM, DM, DM, 2048, (c >> 3) * 128, (c & 7) * 128, 1.f);
    grid_bar(ph0 + 4);

    // Phase E: wheels (4 x 32 tiles) -> out[:, 1024:2048]
    if (c < 128) {
        int w = c >> 5, tt = c & 31;
        gemm_tile<false>(smem, out, wW + (long)w * DM * 256, wb + w * 256,
                         out + 1024 + w * 256,
                         DM, 2048, 256, 2048, (tt >> 1) * 128, (tt & 1) * 128, 1.f);
    }
}

// --------------------------------------------------------------------------
// Launcher: ONE kernel.
// --------------------------------------------------------------------------
extern "C" void kernel_launch(void* const* d_in, const int* in_sizes, int n_in,
                              void* d_out, int out_size)
{
    const float* X    = (const float*)d_in[0];
    const float* Wq   = (const float*)d_in[1];
    const float* Wdkv = (const float*)d_in[2];
    const float* Wuk  = (const float*)d_in[3];
    const float* Wuv  = (const float*)d_in[4];
    const float* Wo   = (const float*)d_in[5];
    const float* wW   = (const float*)d_in[6];
    const float* wb   = (const float*)d_in[7];
    float* out = (float*)d_out;

    float *q, *ckv, *kk, *vv, *ctx;
    cudaGetSymbolAddress((void**)&q,   g_q);
    cudaGetSymbolAddress((void**)&ckv, g_ckv);
    cudaGetSymbolAddress((void**)&kk,  g_k);
    cudaGetSymbolAddress((void**)&vv,  g_v);
    cudaGetSymbolAddress((void**)&ctx, g_ctx);

    const int smem = 45056 * (int)sizeof(unsigned);  // 180224 B
    cudaFuncSetAttribute(mega, cudaFuncAttributeMaxDynamicSharedMemorySize, smem);
    mega<<<NCTA, 256, smem>>>(X, Wq, Wdkv, Wuk, Wuv, Wo, wW, wb, out,
                              q, ckv, kk, vv, ctx);
}

// round 13
// speedup vs baseline: 1.3899x; 1.1731x over previous
#include <cuda_runtime.h>
#include <math.h>

#define SEQ 2048
#define DM  1024
#define NH  16
#define HD  64
#define LAT 256
#define NCTA 148

// Scratch — device globals (no allocation allowed).
__device__ float g_q[SEQ * DM];
__device__ float g_ckv[SEQ * LAT];
__device__ float g_k[SEQ * DM];
__device__ unsigned g_vt[(SEQ / 2) * DM];   // half2 {V[2kp][d], V[2kp+1][d]}
__device__ float g_ctx[SEQ * DM];

// Global software barrier state (zero-initialized).
__device__ unsigned g_cnt;
__device__ volatile unsigned g_phase;

// --------------------------------------------------------------------------
// helpers
// --------------------------------------------------------------------------
__device__ __forceinline__ unsigned f2tf(float x) {
    unsigned r;
    asm("cvt.rna.tf32.f32 %0, %1;" : "=r"(r) : "f"(x));
    return r;
}
__device__ __forceinline__ float fex2(float x) {
    float y;
    asm("ex2.approx.f32 %0, %1;" : "=f"(y) : "f"(x));
    return y;
}
__device__ __forceinline__ unsigned packh2(float lo, float hi) {
    unsigned r;
    asm("cvt.rn.f16x2.f32 %0, %1, %2;" : "=r"(r) : "f"(hi), "f"(lo));
    return r;
}
__device__ __forceinline__ void mma_tf32(float* c, const unsigned* a, const unsigned* b) {
    asm volatile(
        "mma.sync.aligned.m16n8k8.row.col.f32.tf32.tf32.f32 "
        "{%0,%1,%2,%3}, {%4,%5,%6,%7}, {%8,%9}, {%0,%1,%2,%3};"
        : "+f"(c[0]), "+f"(c[1]), "+f"(c[2]), "+f"(c[3])
        : "r"(a[0]), "r"(a[1]), "r"(a[2]), "r"(a[3]),
          "r"(b[0]), "r"(b[1]));
}
__device__ __forceinline__ void mma_f16(float* c, const unsigned* a,
                                        unsigned b0, unsigned b1) {
    asm volatile(
        "mma.sync.aligned.m16n8k16.row.col.f32.f16.f16.f32 "
        "{%0,%1,%2,%3}, {%4,%5,%6,%7}, {%8,%9}, {%0,%1,%2,%3};"
        : "+f"(c[0]), "+f"(c[1]), "+f"(c[2]), "+f"(c[3])
        : "r"(a[0]), "r"(a[1]), "r"(a[2]), "r"(a[3]),
          "r"(b0), "r"(b1));
}
__device__ __forceinline__ void bar_g(int id) {
    asm volatile("bar.sync %0, %1;" :: "r"(id), "r"(128) : "memory");
}

// Grid-wide barrier: all 148 CTAs resident.
__device__ __forceinline__ void grid_bar(unsigned target) {
    __syncthreads();
    if (threadIdx.x == 0) {
        __threadfence();
        unsigned arr = atomicAdd(&g_cnt, 1u);
        if (arr == NCTA - 1) {
            atomicExch(&g_cnt, 0u);
            __threadfence();
            g_phase = target;
        } else {
            while (g_phase != target) { asm volatile("nanosleep.u32 64;"); }
            __threadfence();
        }
    }
    __syncthreads();
}

// --------------------------------------------------------------------------
// GEMM tile (proven body): 256 threads, 128x128 tile, BK=32.
// OCVT: epilogue tf32-converts output*oscale.
// VHALF: epilogue writes pair-major half2 to vt ((unsigned*)C), ignores OCVT.
// --------------------------------------------------------------------------
#define AP 36
#define BP 132
template <bool OCVT, bool VHALF>
__device__ void gemm_tile(unsigned* smem,
    const float* __restrict__ A, const float* __restrict__ B,
    const float* __restrict__ bias, float* __restrict__ C,
    int K, int lda, int ldb, int ldc, int m0, int n0, float oscale)
{
    unsigned* As = smem;
    unsigned* Bs = smem + 128 * AP;

    const int tid  = threadIdx.x;
    const int lane = tid & 31;
    const int warp = tid >> 5;
    const int g = lane >> 2;
    const int r = lane & 3;
    const int wm = warp & 3;
    const int wn = warp >> 2;

    float acc[2][8][4];
    #pragma unroll
    for (int i = 0; i < 2; i++)
        #pragma unroll
        for (int j = 0; j < 8; j++)
            #pragma unroll
            for (int t = 0; t < 4; t++) acc[i][j][t] = 0.f;

    for (int k0 = 0; k0 < K; k0 += 32) {
        #pragma unroll
        for (int e = 0; e < 16; e++) {
            int idx = e * 256 + tid;
            int m = idx >> 5, kk = idx & 31;
            As[m * AP + kk] = f2tf(A[(long)(m0 + m) * lda + k0 + kk]);
        }
        #pragma unroll
        for (int e = 0; e < 16; e++) {
            int idx = e * 256 + tid;
            int kk = idx >> 7, n = idx & 127;
            Bs[kk * BP + n] = f2tf(B[(long)(k0 + kk) * ldb + n0 + n]);
        }
        __syncthreads();

        #pragma unroll
        for (int ks = 0; ks < 4; ks++) {
            const int k = ks * 8;
            unsigned a[2][4], b[8][2];
            #pragma unroll
            for (int i = 0; i < 2; i++) {
                int row = wm * 32 + i * 16;
                a[i][0] = As[(row + g)     * AP + k + r];
                a[i][1] = As[(row + g + 8) * AP + k + r];
                a[i][2] = As[(row + g)     * AP + k + r + 4];
                a[i][3] = As[(row + g + 8) * AP + k + r + 4];
            }
            #pragma unroll
            for (int j = 0; j < 8; j++) {
                int col = wn * 64 + j * 8;
                b[j][0] = Bs[(k + r)     * BP + col + g];
                b[j][1] = Bs[(k + r + 4) * BP + col + g];
            }
            #pragma unroll
            for (int i = 0; i < 2; i++)
                #pragma unroll
                for (int j = 0; j < 8; j++)
                    mma_tf32(acc[i][j], a[i], b[j]);
        }
        __syncthreads();
    }

    #pragma unroll
    for (int i = 0; i < 2; i++) {
        int row = m0 + wm * 32 + i * 16;
        #pragma unroll
        for (int j = 0; j < 8; j++) {
            int col = n0 + wn * 64 + j * 8 + 2 * r;
            float c00 = acc[i][j][0], c01 = acc[i][j][1];
            float c10 = acc[i][j][2], c11 = acc[i][j][3];
            if (VHALF) {
                // pair rows (row+g, row+g+1) and (row+g+8, row+g+9)
                float d00 = __shfl_down_sync(0xffffffffu, c00, 4);
                float d01 = __shfl_down_sync(0xffffffffu, c01, 4);
                float d10 = __shfl_down_sync(0xffffffffu, c10, 4);
                float d11 = __shfl_down_sync(0xffffffffu, c11, 4);
                if (!(g & 1)) {
                    unsigned* vt = (unsigned*)C;
                    int kp  = (row + g) >> 1;
                    int kp2 = (row + g + 8) >> 1;
                    uint2 v0 = make_uint2(packh2(c00, d00), packh2(c01, d01));
                    uint2 v1 = make_uint2(packh2(c10, d10), packh2(c11, d11));
                    *reinterpret_cast<uint2*>(&vt[(long)kp  * DM + col]) = v0;
                    *reinterpret_cast<uint2*>(&vt[(long)kp2 * DM + col]) = v1;
                }
            } else {
                float b0 = 0.f, b1 = 0.f;
                if (bias) { b0 = bias[col]; b1 = bias[col + 1]; }
                c00 += b0; c01 += b1; c10 += b0; c11 += b1;
                if (OCVT) {
                    c00 = __uint_as_float(f2tf(c00 * oscale));
                    c01 = __uint_as_float(f2tf(c01 * oscale));
                    c10 = __uint_as_float(f2tf(c10 * oscale));
                    c11 = __uint_as_float(f2tf(c11 * oscale));
                }
                *reinterpret_cast<float2*>(&C[(long)(row + g) * ldc + col]) =
                    make_float2(c00, c01);
                *reinterpret_cast<float2*>(&C[(long)(row + g + 8) * ldc + col]) =
                    make_float2(c10, c11);
            }
        }
    }
}

// --------------------------------------------------------------------------
// Flash group: 4 warps / 128 threads, 128 queries, 32 rows per warp.
// S-phase: tf32 (proven). PV-phase: fp16 m16n8k16 — P fragments built from
// S c-frags by register cvt (NO smem roundtrip), V read from pair-major VT.
// Group smem: KB 5120 w, VT 32*72=2304 w, QB 10752 w -> 18176 w.
// --------------------------------------------------------------------------
__device__ void flash_group(unsigned* KB, int barid, int h, int i0,
    const float* __restrict__ q, const float* __restrict__ k,
    const unsigned* __restrict__ vt, float* __restrict__ ctx)
{
    unsigned* VT = KB + 5120;
    unsigned* QB = KB + 7424;

    const int tid  = threadIdx.x & 127;
    const int lane = tid & 31;
    const int warp = tid >> 5;
    const int g = lane >> 2;
    const int r = lane & 3;
    const int wbase = warp * 2688;

    // Stage Q (tf32 bits, pre-scaled by 0.125*log2e)
    #pragma unroll
    for (int e = 0; e < 16; e++) {
        int idx = e * 128 + tid;
        int row = idx >> 4, dq = idx & 15;
        uint4 q4 = *reinterpret_cast<const uint4*>(
            &q[(long)(i0 + row) * DM + h * HD + dq * 4]);
        unsigned* p = &QB[(row >> 5) * 2688 + (row & 31) * 84 + dq];
        p[0]  = q4.x;
        p[20] = q4.y;
        p[40] = q4.z;
        p[60] = q4.w;
    }
    bar_g(barid);

    unsigned qa[2][8][4];
    #pragma unroll
    for (int i = 0; i < 2; i++) {
        const uint4* lo4 = reinterpret_cast<const uint4*>(
            &QB[wbase + (i * 16 + g) * 84 + r * 20]);
        const uint4* hi4 = reinterpret_cast<const uint4*>(
            &QB[wbase + (i * 16 + g + 8) * 84 + r * 20]);
        uint4 L[4] = {lo4[0], lo4[1], lo4[2], lo4[3]};
        uint4 H[4] = {hi4[0], hi4[1], hi4[2], hi4[3]};
        const unsigned* lo = reinterpret_cast<const unsigned*>(L);
        const unsigned* hi = reinterpret_cast<const unsigned*>(H);
        #pragma unroll
        for (int kt = 0; kt < 8; kt++) {
            qa[i][kt][0] = lo[2 * kt];
            qa[i][kt][1] = hi[2 * kt];
            qa[i][kt][2] = lo[2 * kt + 1];
            qa[i][kt][3] = hi[2 * kt + 1];
        }
    }

    float lsum[2][2];
    lsum[0][0] = lsum[0][1] = lsum[1][0] = lsum[1][1] = 0.f;
    float o[2][8][4];
    #pragma unroll
    for (int i = 0; i < 2; i++)
        #pragma unroll
        for (int j = 0; j < 8; j++)
            #pragma unroll
            for (int t = 0; t < 4; t++) o[i][j][t] = 0.f;

    for (int j0 = 0; j0 < SEQ; j0 += 64) {
        // ---- Stage K (tf32 frag layout) ----
        #pragma unroll
        for (int e = 0; e < 4; e++) {
            int idx = e * 128 + tid;
            int key = idx >> 1, dh = idx & 1;       // 2 threads per key row
            long gbase = (long)(j0 + key) * DM + h * HD + dh * 32;
            #pragma unroll
            for (int u = 0; u < 2; u++) {
                uint4 k4 = *reinterpret_cast<const uint4*>(&k[gbase + u * 4 + (u >> 0) * 0]);
                // dims dh*32 + u*4 .. +3  (two uint4 = 8 dims per thread? need 32)
                (void)k4;
            }
        }
        // simpler proven staging (same as R12): 8 uint4 dims per thread pair
        #pragma unroll
        for (int e = 0; e < 8; e++) {
            int idx = e * 128 + tid;
            int key = idx >> 4, dq = idx & 15;
            if (e < 8) {
                // K only needs 4 iters worth (64 keys x 16 dq over 128 thr = 8 iters of K alone)
            }
            long gbase = (long)(j0 + key) * DM + h * HD + dq * 4;
            if (idx < 64 * 16) {
                uint4 k4 = *reinterpret_cast<const uint4*>(&k[gbase]);
                unsigned* kp = &KB[key * 80 + dq];
                kp[0]  = k4.x;
                kp[20] = k4.y;
                kp[40] = k4.z;
                kp[60] = k4.w;
            }
        }
        // ---- Stage VT (pure bit copy from pair-major vt) ----
        #pragma unroll
        for (int e = 0; e < 4; e++) {
            int idx = e * 128 + tid;
            int kp = idx >> 4, dq = idx & 15;
            uint4 v4 = *reinterpret_cast<const uint4*>(
                &vt[(long)((j0 >> 1) + kp) * DM + h * HD + dq * 4]);
            *reinterpret_cast<uint4*>(&VT[kp * 72 + dq * 4]) = v4;
        }
        bar_g(barid);

        #pragma unroll
        for (int half = 0; half < 2; half++) {
            const int nb = half * 4;

            // ---- S = Q @ K^T (tf32) ----
            float s[2][4][4];
            #pragma unroll
            for (int nt = 0; nt < 4; nt++) {
                #pragma unroll
                for (int i = 0; i < 2; i++)
                    #pragma unroll
                    for (int t = 0; t < 4; t++) s[i][nt][t] = 0.f;
                const uint4* kp4 = reinterpret_cast<const uint4*>(
                    &KB[((nb + nt) * 8 + g) * 80 + r * 20]);
                uint4 W[4] = {kp4[0], kp4[1], kp4[2], kp4[3]};
                const unsigned* w = reinterpret_cast<const unsigned*>(W);
                #pragma unroll
                for (int kt = 0; kt < 8; kt++) {
                    unsigned b[2] = {w[2 * kt], w[2 * kt + 1]};
                    mma_tf32(s[0][nt], qa[0][kt], b);
                    mma_tf32(s[1][nt], qa[1][kt], b);
                }
            }

            // ---- P = 2^S; row sums ----
            #pragma unroll
            for (int i = 0; i < 2; i++)
                #pragma unroll
                for (int nt = 0; nt < 4; nt++) {
                    s[i][nt][0] = fex2(s[i][nt][0]);
                    s[i][nt][1] = fex2(s[i][nt][1]);
                    s[i][nt][2] = fex2(s[i][nt][2]);
                    s[i][nt][3] = fex2(s[i][nt][3]);
                    lsum[i][0] += s[i][nt][0] + s[i][nt][1];
                    lsum[i][1] += s[i][nt][2] + s[i][nt][3];
                }

            // ---- P A-frags (fp16, pure register packs) ----
            unsigned pa[2][2][4];
            #pragma unroll
            for (int i = 0; i < 2; i++)
                #pragma unroll
                for (int kt2 = 0; kt2 < 2; kt2++) {
                    pa[i][kt2][0] = packh2(s[i][2 * kt2][0],     s[i][2 * kt2][1]);
                    pa[i][kt2][1] = packh2(s[i][2 * kt2][2],     s[i][2 * kt2][3]);
                    pa[i][kt2][2] = packh2(s[i][2 * kt2 + 1][0], s[i][2 * kt2 + 1][1]);
                    pa[i][kt2][3] = packh2(s[i][2 * kt2 + 1][2], s[i][2 * kt2 + 1][3]);
                }

            // ---- O += P @ V (fp16 m16n8k16) ----
            #pragma unroll
            for (int kt2 = 0; kt2 < 2; kt2++) {
                const int kpb = half * 16 + kt2 * 8;
                #pragma unroll
                for (int nt = 0; nt < 8; nt++) {
                    unsigned b0 = VT[(kpb + r)     * 72 + nt * 8 + g];
                    unsigned b1 = VT[(kpb + r + 4) * 72 + nt * 8 + g];
                    mma_f16(o[0][nt], pa[0][kt2], b0, b1);
                    mma_f16(o[1][nt], pa[1][kt2], b0, b1);
                }
            }
        }
        bar_g(barid);
    }

    const int qb = warp * 32;
    #pragma unroll
    for (int i = 0; i < 2; i++) {
        float l0 = lsum[i][0], l1 = lsum[i][1];
        l0 += __shfl_xor_sync(0xffffffffu, l0, 1);
        l0 += __shfl_xor_sync(0xffffffffu, l0, 2);
        l1 += __shfl_xor_sync(0xffffffffu, l1, 1);
        l1 += __shfl_xor_sync(0xffffffffu, l1, 2);
        float inv0 = 1.0f / l0, inv1 = 1.0f / l1;
        #pragma unroll
        for (int nt = 0; nt < 8; nt++) {
            int col = h * HD + nt * 8 + 2 * r;
            *reinterpret_cast<float2*>(
                &ctx[(long)(i0 + qb + i * 16 + g) * DM + col]) =
                make_float2(o[i][nt][0] * inv0, o[i][nt][1] * inv0);
            *reinterpret_cast<float2*>(
                &ctx[(long)(i0 + qb + i * 16 + g + 8) * DM + col]) =
                make_float2(o[i][nt][2] * inv1, o[i][nt][3] * inv1);
        }
    }
}

// --------------------------------------------------------------------------
// Persistent mega-kernel: 148 CTAs x 256 threads, software grid barriers.
// --------------------------------------------------------------------------
__global__ void __launch_bounds__(256, 1) mega(
    const float* __restrict__ X,  const float* __restrict__ Wq,
    const float* __restrict__ Wdkv, const float* __restrict__ Wuk,
    const float* __restrict__ Wuv, const float* __restrict__ Wo,
    const float* __restrict__ wW, const float* __restrict__ wb,
    float* __restrict__ out,
    float* __restrict__ q, float* __restrict__ ckv,
    float* __restrict__ kk, unsigned* __restrict__ vt,
    float* __restrict__ ctx)
{
    extern __shared__ unsigned smem[];
    const unsigned ph0 = g_phase;
    const int c = blockIdx.x;
    const float QSCALE = 0.125f * 1.4426950408889634f;

    // Phase A: 32 ckv + 116 q
    if (c < 32) {
        gemm_tile<false, false>(smem, X, Wdkv, nullptr, ckv,
                                DM, DM, LAT, LAT, (c >> 1) * 128, (c & 1) * 128, 1.f);
    } else {
        int qi = c - 32;
        gemm_tile<true, false>(smem, X, Wq, nullptr, q,
                               DM, DM, DM, DM, (qi >> 3) * 128, (qi & 7) * 128, QSCALE);
    }
    grid_bar(ph0 + 1);

    // Phase B: 128 k + 128 v + 12 leftover q
    for (int t = c; t < 268; t += NCTA) {
        if (t < 128) {
            gemm_tile<true, false>(smem, ckv, Wuk, nullptr, kk,
                                   LAT, LAT, DM, DM, (t >> 3) * 128, (t & 7) * 128, 1.f);
        } else if (t < 256) {
            int tt = t - 128;
            gemm_tile<false, true>(smem, ckv, Wuv, nullptr, (float*)vt,
                                   LAT, LAT, DM, DM, (tt >> 3) * 128, (tt & 7) * 128, 1.f);
        } else {
            int qi = 116 + (t - 256);
            gemm_tile<true, false>(smem, X, Wq, nullptr, q,
                                   DM, DM, DM, DM, (qi >> 3) * 128, (qi & 7) * 128, QSCALE);
        }
    }
    grid_bar(ph0 + 2);

    // Phase C: flash — two 4-warp groups per CTA
    {
        int group = threadIdx.x >> 7;
        int t = c * 2 + group;
        if (t < 256)
            flash_group(smem + group * 18176, 1 + group,
                        t >> 4, (t & 15) * 128, q, kk, vt, ctx);
    }
    grid_bar(ph0 + 3);

    // Phase D: body
    if (c < 128)
        gemm_tile<false, false>(smem, ctx, Wo, nullptr, out,
                                DM, DM, DM, 2048, (c >> 3) * 128, (c & 7) * 128, 1.f);
    grid_bar(ph0 + 4);

    // Phase E: wheels
    if (c < 128) {
        int w = c >> 5, tt = c & 31;
        gemm_tile<false, false>(smem, out, wW + (long)w * DM * 256, wb + w * 256,
                                out + 1024 + w * 256,
                                DM, 2048, 256, 2048, (tt >> 1) * 128, (tt & 1) * 128, 1.f);
    }
}

// --------------------------------------------------------------------------
// Launcher: ONE kernel.
// --------------------------------------------------------------------------
extern "C" void kernel_launch(void* const* d_in, const int* in_sizes, int n_in,
                              void* d_out, int out_size)
{
    const float* X    = (const float*)d_in[0];
    const float* Wq   = (const float*)d_in[1];
    const float* Wdkv = (const float*)d_in[2];
    const float* Wuk  = (const float*)d_in[3];
    const float* Wuv  = (const float*)d_in[4];
    const float* Wo   = (const float*)d_in[5];
    const float* wW   = (const float*)d_in[6];
    const float* wb   = (const float*)d_in[7];
    float* out = (float*)d_out;

    float *q, *ckv, *kk, *ctx;
    unsigned* vt;
    cudaGetSymbolAddress((void**)&q,   g_q);
    cudaGetSymbolAddress((void**)&ckv, g_ckv);
    cudaGetSymbolAddress((void**)&kk,  g_k);
    cudaGetSymbolAddress((void**)&vt,  g_vt);
    cudaGetSymbolAddress((void**)&ctx, g_ctx);

    const int smem = 36352 * (int)sizeof(unsigned);  // 145408 B
    cudaFuncSetAttribute(mega, cudaFuncAttributeMaxDynamicSharedMemorySize, smem);
    mega<<<NCTA, 256, smem>>>(X, Wq, Wdkv, Wuk, Wuv, Wo, wW, wb, out,
                              q, ckv, kk, vt, ctx);
}

// round 14
// speedup vs baseline: 1.5572x; 1.1203x over previous
#include <cuda_runtime.h>
#include <math.h>

#define SEQ 2048
#define DM  1024
#define NH  16
#define HD  64
#define LAT 256
#define NCTA 148

// Scratch — device globals (no allocation allowed).
__device__ unsigned g_qh[SEQ * (DM / 2)];   // half2 {q[r][2p], q[r][2p+1]} pre-scaled
__device__ float    g_ckv[SEQ * LAT];
__device__ unsigned g_kh[SEQ * (DM / 2)];   // half2 col pairs
__device__ unsigned g_vt[(SEQ / 2) * DM];   // half2 {V[2kp][d], V[2kp+1][d]}
__device__ float    g_ctx[SEQ * DM];

// Global software barrier state (zero-initialized).
__device__ unsigned g_cnt;
__device__ volatile unsigned g_phase;

// --------------------------------------------------------------------------
// helpers
// --------------------------------------------------------------------------
__device__ __forceinline__ unsigned f2tf(float x) {
    unsigned r;
    asm("cvt.rna.tf32.f32 %0, %1;" : "=r"(r) : "f"(x));
    return r;
}
__device__ __forceinline__ float fex2(float x) {
    float y;
    asm("ex2.approx.f32 %0, %1;" : "=f"(y) : "f"(x));
    return y;
}
__device__ __forceinline__ unsigned packh2(float lo, float hi) {
    unsigned r;
    asm("cvt.rn.f16x2.f32 %0, %1, %2;" : "=r"(r) : "f"(hi), "f"(lo));
    return r;
}
__device__ __forceinline__ void mma_tf32(float* c, const unsigned* a, const unsigned* b) {
    asm volatile(
        "mma.sync.aligned.m16n8k8.row.col.f32.tf32.tf32.f32 "
        "{%0,%1,%2,%3}, {%4,%5,%6,%7}, {%8,%9}, {%0,%1,%2,%3};"
        : "+f"(c[0]), "+f"(c[1]), "+f"(c[2]), "+f"(c[3])
        : "r"(a[0]), "r"(a[1]), "r"(a[2]), "r"(a[3]),
          "r"(b[0]), "r"(b[1]));
}
__device__ __forceinline__ void mma_f16(float* c, const unsigned* a,
                                        unsigned b0, unsigned b1) {
    asm volatile(
        "mma.sync.aligned.m16n8k16.row.col.f32.f16.f16.f32 "
        "{%0,%1,%2,%3}, {%4,%5,%6,%7}, {%8,%9}, {%0,%1,%2,%3};"
        : "+f"(c[0]), "+f"(c[1]), "+f"(c[2]), "+f"(c[3])
        : "r"(a[0]), "r"(a[1]), "r"(a[2]), "r"(a[3]),
          "r"(b0), "r"(b1));
}
__device__ __forceinline__ void bar_g(int id) {
    asm volatile("bar.sync %0, %1;" :: "r"(id), "r"(128) : "memory");
}

// Grid-wide barrier: all 148 CTAs resident.
__device__ __forceinline__ void grid_bar(unsigned target) {
    __syncthreads();
    if (threadIdx.x == 0) {
        __threadfence();
        unsigned arr = atomicAdd(&g_cnt, 1u);
        if (arr == NCTA - 1) {
            atomicExch(&g_cnt, 0u);
            __threadfence();
            g_phase = target;
        } else {
            while (g_phase != target) { asm volatile("nanosleep.u32 64;"); }
            __threadfence();
        }
    }
    __syncthreads();
}

// --------------------------------------------------------------------------
// GEMM tile (proven body): 256 threads, 128x128 tile, BK=32, tf32 mma.
// MODE 0: fp32 out (+bias). MODE 2: half2 col-pair pack (*oscale) -> uint* C.
// MODE 3: half2 pair-major rows (V transpose-pack) -> uint* C.
// --------------------------------------------------------------------------
#define AP 36
#define BP 132
template <int MODE>
__device__ void gemm_tile(unsigned* smem,
    const float* __restrict__ A, const float* __restrict__ B,
    const float* __restrict__ bias, float* __restrict__ C,
    int K, int lda, int ldb, int ldc, int m0, int n0, float oscale)
{
    unsigned* As = smem;
    unsigned* Bs = smem + 128 * AP;

    const int tid  = threadIdx.x;
    const int lane = tid & 31;
    const int warp = tid >> 5;
    const int g = lane >> 2;
    const int r = lane & 3;
    const int wm = warp & 3;
    const int wn = warp >> 2;

    float acc[2][8][4];
    #pragma unroll
    for (int i = 0; i < 2; i++)
        #pragma unroll
        for (int j = 0; j < 8; j++)
            #pragma unroll
            for (int t = 0; t < 4; t++) acc[i][j][t] = 0.f;

    for (int k0 = 0; k0 < K; k0 += 32) {
        #pragma unroll
        for (int e = 0; e < 16; e++) {
            int idx = e * 256 + tid;
            int m = idx >> 5, kk = idx & 31;
            As[m * AP + kk] = f2tf(A[(long)(m0 + m) * lda + k0 + kk]);
        }
        #pragma unroll
        for (int e = 0; e < 16; e++) {
            int idx = e * 256 + tid;
            int kk = idx >> 7, n = idx & 127;
            Bs[kk * BP + n] = f2tf(B[(long)(k0 + kk) * ldb + n0 + n]);
        }
        __syncthreads();

        #pragma unroll
        for (int ks = 0; ks < 4; ks++) {
            const int k = ks * 8;
            unsigned a[2][4], b[8][2];
            #pragma unroll
            for (int i = 0; i < 2; i++) {
                int row = wm * 32 + i * 16;
                a[i][0] = As[(row + g)     * AP + k + r];
                a[i][1] = As[(row + g + 8) * AP + k + r];
                a[i][2] = As[(row + g)     * AP + k + r + 4];
                a[i][3] = As[(row + g + 8) * AP + k + r + 4];
            }
            #pragma unroll
            for (int j = 0; j < 8; j++) {
                int col = wn * 64 + j * 8;
                b[j][0] = Bs[(k + r)     * BP + col + g];
                b[j][1] = Bs[(k + r + 4) * BP + col + g];
            }
            #pragma unroll
            for (int i = 0; i < 2; i++)
                #pragma unroll
                for (int j = 0; j < 8; j++)
                    mma_tf32(acc[i][j], a[i], b[j]);
        }
        __syncthreads();
    }

    #pragma unroll
    for (int i = 0; i < 2; i++) {
        int row = m0 + wm * 32 + i * 16;
        #pragma unroll
        for (int j = 0; j < 8; j++) {
            int col = n0 + wn * 64 + j * 8 + 2 * r;
            float c00 = acc[i][j][0], c01 = acc[i][j][1];
            float c10 = acc[i][j][2], c11 = acc[i][j][3];
            if (MODE == 3) {
                // pair rows: (row+g, row+g+1), (row+g+8, row+g+9)
                float d00 = __shfl_down_sync(0xffffffffu, c00, 4);
                float d01 = __shfl_down_sync(0xffffffffu, c01, 4);
                float d10 = __shfl_down_sync(0xffffffffu, c10, 4);
                float d11 = __shfl_down_sync(0xffffffffu, c11, 4);
                if (!(g & 1)) {
                    unsigned* vt = (unsigned*)C;
                    int kp  = (row + g) >> 1;
                    int kp2 = (row + g + 8) >> 1;
                    uint2 v0 = make_uint2(packh2(c00, d00), packh2(c01, d01));
                    uint2 v1 = make_uint2(packh2(c10, d10), packh2(c11, d11));
                    *reinterpret_cast<uint2*>(&vt[(long)kp  * DM + col]) = v0;
                    *reinterpret_cast<uint2*>(&vt[(long)kp2 * DM + col]) = v1;
                }
            } else if (MODE == 2) {
                // pack adjacent cols into half2 (scaled)
                unsigned* ch = (unsigned*)C;
                int ldh = ldc >> 1;
                ch[(long)(row + g)     * ldh + (col >> 1)] =
                    packh2(c00 * oscale, c01 * oscale);
                ch[(long)(row + g + 8) * ldh + (col >> 1)] =
                    packh2(c10 * oscale, c11 * oscale);
            } else {
                float b0 = 0.f, b1 = 0.f;
                if (bias) { b0 = bias[col]; b1 = bias[col + 1]; }
                *reinterpret_cast<float2*>(&C[(long)(row + g) * ldc + col]) =
                    make_float2(c00 + b0, c01 + b1);
                *reinterpret_cast<float2*>(&C[(long)(row + g + 8) * ldc + col]) =
                    make_float2(c10 + b0, c11 + b1);
            }
        }
    }
}

// --------------------------------------------------------------------------
// Flash group — FULL fp16 m16n8k16 path. 4 warps / 128 threads, 128
// queries, 32 rows per warp. Q/K arrive as packed half2 col pairs; V as
// pair-major half2 (VT). P never touches smem (register f16x2 packs).
//
// Segment layout for Q/K half2 words (32 pairs/row):
//   addr = row*48 + (pair&3)*12 + (pair>>2)
// Fragment read: uint4 at row*48 + r*12 (+4) -> j=0..7 = chunks kt=0..3
// interleaved (b0=j2kt, b1=j2kt+1). Bank-verified conflict-free.
// Group smem: KB 3072 + VT 2304 + QB 4*1536 = 11520 w (46080 B).
// --------------------------------------------------------------------------
__device__ void flash_group(unsigned* KB, int barid, int h, int i0,
    const unsigned* __restrict__ qh, const unsigned* __restrict__ kh,
    const unsigned* __restrict__ vt, float* __restrict__ ctx)
{
    unsigned* VT = KB + 3072;
    unsigned* QB = KB + 5376;

    const int tid  = threadIdx.x & 127;
    const int lane = tid & 31;
    const int warp = tid >> 5;
    const int g = lane >> 2;
    const int r = lane & 3;
    const int wbase = warp * 1536;

    // ---- Stage Q (packed half2, pre-scaled): 128 rows x 8 uint4 ----
    #pragma unroll
    for (int e = 0; e < 8; e++) {
        int idx = e * 128 + tid;
        int row = idx >> 3, t = idx & 7;
        uint4 q4 = *reinterpret_cast<const uint4*>(
            &qh[(long)(i0 + row) * (DM / 2) + h * 32 + t * 4]);
        unsigned* p = &QB[(row >> 5) * 1536 + (row & 31) * 48 + t];
        p[0]  = q4.x;
        p[12] = q4.y;
        p[24] = q4.z;
        p[36] = q4.w;
    }
    bar_g(barid);

    // ---- Q A-fragments (fp16): qa[i][kt][0..3] ----
    unsigned qa[2][4][4];
    #pragma unroll
    for (int i = 0; i < 2; i++) {
        const uint4* lo4 = reinterpret_cast<const uint4*>(
            &QB[wbase + (i * 16 + g) * 48 + r * 12]);
        const uint4* hi4 = reinterpret_cast<const uint4*>(
            &QB[wbase + (i * 16 + g + 8) * 48 + r * 12]);
        uint4 L[2] = {lo4[0], lo4[1]};
        uint4 H[2] = {hi4[0], hi4[1]};
        const unsigned* lo = reinterpret_cast<const unsigned*>(L);
        const unsigned* hi = reinterpret_cast<const unsigned*>(H);
        #pragma unroll
        for (int kt = 0; kt < 4; kt++) {
            qa[i][kt][0] = lo[2 * kt];
            qa[i][kt][1] = hi[2 * kt];
            qa[i][kt][2] = lo[2 * kt + 1];
            qa[i][kt][3] = hi[2 * kt + 1];
        }
    }

    float lsum[2][2];
    lsum[0][0] = lsum[0][1] = lsum[1][0] = lsum[1][1] = 0.f;
    float o[2][8][4];
    #pragma unroll
    for (int i = 0; i < 2; i++)
        #pragma unroll
        for (int j = 0; j < 8; j++)
            #pragma unroll
            for (int t = 0; t < 4; t++) o[i][j][t] = 0.f;

    for (int j0 = 0; j0 < SEQ; j0 += 64) {
        // ---- Stage K: 64 keys x 8 uint4 = 512 items, 4 iters ----
        #pragma unroll
        for (int e = 0; e < 4; e++) {
            int idx = e * 128 + tid;
            int key = idx >> 3, t = idx & 7;
            uint4 k4 = *reinterpret_cast<const uint4*>(
                &kh[(long)(j0 + key) * (DM / 2) + h * 32 + t * 4]);
            unsigned* p = &KB[key * 48 + t];
            p[0]  = k4.x;
            p[12] = k4.y;
            p[24] = k4.z;
            p[36] = k4.w;
        }
        // ---- Stage VT (pair-major half2, pure bit copy) ----
        #pragma unroll
        for (int e = 0; e < 4; e++) {
            int idx = e * 128 + tid;
            int kp = idx >> 4, dq = idx & 15;
            uint4 v4 = *reinterpret_cast<const uint4*>(
                &vt[(long)((j0 >> 1) + kp) * DM + h * HD + dq * 4]);
            *reinterpret_cast<uint4*>(&VT[kp * 72 + dq * 4]) = v4;
        }
        bar_g(barid);

        #pragma unroll
        for (int half = 0; half < 2; half++) {
            const int nb = half * 4;

            // ---- S = Q @ K^T (fp16 k16) ----
            float s[2][4][4];
            #pragma unroll
            for (int nt = 0; nt < 4; nt++) {
                #pragma unroll
                for (int i = 0; i < 2; i++)
                    #pragma unroll
                    for (int t = 0; t < 4; t++) s[i][nt][t] = 0.f;
                const uint4* kp4 = reinterpret_cast<const uint4*>(
                    &KB[((nb + nt) * 8 + g) * 48 + r * 12]);
                uint4 W0 = kp4[0], W1 = kp4[1];
                unsigned w[8] = {W0.x, W0.y, W0.z, W0.w, W1.x, W1.y, W1.z, W1.w};
                #pragma unroll
                for (int kt = 0; kt < 4; kt++) {
                    mma_f16(s[0][nt], qa[0][kt], w[2 * kt], w[2 * kt + 1]);
                    mma_f16(s[1][nt], qa[1][kt], w[2 * kt], w[2 * kt + 1]);
                }
            }

            // ---- P = 2^S; row sums ----
            #pragma unroll
            for (int i = 0; i < 2; i++)
                #pragma unroll
                for (int nt = 0; nt < 4; nt++) {
                    s[i][nt][0] = fex2(s[i][nt][0]);
                    s[i][nt][1] = fex2(s[i][nt][1]);
                    s[i][nt][2] = fex2(s[i][nt][2]);
                    s[i][nt][3] = fex2(s[i][nt][3]);
                    lsum[i][0] += s[i][nt][0] + s[i][nt][1];
                    lsum[i][1] += s[i][nt][2] + s[i][nt][3];
                }

            // ---- P A-frags (fp16, pure register packs) ----
            unsigned pa[2][2][4];
            #pragma unroll
            for (int i = 0; i < 2; i++)
                #pragma unroll
                for (int kt2 = 0; kt2 < 2; kt2++) {
                    pa[i][kt2][0] = packh2(s[i][2 * kt2][0],     s[i][2 * kt2][1]);
                    pa[i][kt2][1] = packh2(s[i][2 * kt2][2],     s[i][2 * kt2][3]);
                    pa[i][kt2][2] = packh2(s[i][2 * kt2 + 1][0], s[i][2 * kt2 + 1][1]);
                    pa[i][kt2][3] = packh2(s[i][2 * kt2 + 1][2], s[i][2 * kt2 + 1][3]);
                }

            // ---- O += P @ V (fp16 k16) ----
            #pragma unroll
            for (int kt2 = 0; kt2 < 2; kt2++) {
                const int kpb = half * 16 + kt2 * 8;
                #pragma unroll
                for (int nt = 0; nt < 8; nt++) {
                    unsigned b0 = VT[(kpb + r)     * 72 + nt * 8 + g];
                    unsigned b1 = VT[(kpb + r + 4) * 72 + nt * 8 + g];
                    mma_f16(o[0][nt], pa[0][kt2], b0, b1);
                    mma_f16(o[1][nt], pa[1][kt2], b0, b1);
                }
            }
        }
        bar_g(barid);
    }

    const int qb = warp * 32;
    #pragma unroll
    for (int i = 0; i < 2; i++) {
        float l0 = lsum[i][0], l1 = lsum[i][1];
        l0 += __shfl_xor_sync(0xffffffffu, l0, 1);
        l0 += __shfl_xor_sync(0xffffffffu, l0, 2);
        l1 += __shfl_xor_sync(0xffffffffu, l1, 1);
        l1 += __shfl_xor_sync(0xffffffffu, l1, 2);
        float inv0 = 1.0f / l0, inv1 = 1.0f / l1;
        #pragma unroll
        for (int nt = 0; nt < 8; nt++) {
            int col = h * HD + nt * 8 + 2 * r;
            *reinterpret_cast<float2*>(
                &ctx[(long)(i0 + qb + i * 16 + g) * DM + col]) =
                make_float2(o[i][nt][0] * inv0, o[i][nt][1] * inv0);
            *reinterpret_cast<float2*>(
                &ctx[(long)(i0 + qb + i * 16 + g + 8) * DM + col]) =
                make_float2(o[i][nt][2] * inv1, o[i][nt][3] * inv1);
        }
    }
}

// --------------------------------------------------------------------------
// Persistent mega-kernel: 148 CTAs x 256 threads, software grid barriers.
// --------------------------------------------------------------------------
__global__ void __launch_bounds__(256, 1) mega(
    const float* __restrict__ X,  const float* __restrict__ Wq,
    const float* __restrict__ Wdkv, const float* __restrict__ Wuk,
    const float* __restrict__ Wuv, const float* __restrict__ Wo,
    const float* __restrict__ wW, const float* __restrict__ wb,
    float* __restrict__ out,
    unsigned* __restrict__ qh, float* __restrict__ ckv,
    unsigned* __restrict__ kh, unsigned* __restrict__ vt,
    float* __restrict__ ctx)
{
    extern __shared__ unsigned smem[];
    const unsigned ph0 = g_phase;
    const int c = blockIdx.x;
    const float QSCALE = 0.125f * 1.4426950408889634f;

    // Phase A: 32 ckv + 116 q
    if (c < 32) {
        gemm_tile<0>(smem, X, Wdkv, nullptr, ckv,
                     DM, DM, LAT, LAT, (c >> 1) * 128, (c & 1) * 128, 1.f);
    } else {
        int qi = c - 32;
        gemm_tile<2>(smem, X, Wq, nullptr, (float*)qh,
                     DM, DM, DM, DM, (qi >> 3) * 128, (qi & 7) * 128, QSCALE);
    }
    grid_bar(ph0 + 1);

    // Phase B: 128 k + 128 v + 12 leftover q
    for (int t = c; t < 268; t += NCTA) {
        if (t < 128) {
            gemm_tile<2>(smem, ckv, Wuk, nullptr, (float*)kh,
                         LAT, LAT, DM, DM, (t >> 3) * 128, (t & 7) * 128, 1.f);
        } else if (t < 256) {
            int tt = t - 128;
            gemm_tile<3>(smem, ckv, Wuv, nullptr, (float*)vt,
                         LAT, LAT, DM, DM, (tt >> 3) * 128, (tt & 7) * 128, 1.f);
        } else {
            int qi = 116 + (t - 256);
            gemm_tile<2>(smem, X, Wq, nullptr, (float*)qh,
                         DM, DM, DM, DM, (qi >> 3) * 128, (qi & 7) * 128, QSCALE);
        }
    }
    grid_bar(ph0 + 2);

    // Phase C: flash — two 4-warp groups per CTA, 256 (head, qtile) tasks
    {
        int group = threadIdx.x >> 7;
        int t = c * 2 + group;
        if (t < 256)
            flash_group(smem + group * 11520, 1 + group,
                        t >> 4, (t & 15) * 128, qh, kh, vt, ctx);
    }
    grid_bar(ph0 + 3);

    // Phase D: body
    if (c < 128)
        gemm_tile<0>(smem, ctx, Wo, nullptr, out,
                     DM, DM, DM, 2048, (c >> 3) * 128, (c & 7) * 128, 1.f);
    grid_bar(ph0 + 4);

    // Phase E: wheels
    if (c < 128) {
        int w = c >> 5, tt = c & 31;
        gemm_tile<0>(smem, out, wW + (long)w * DM * 256, wb + w * 256,
                     out + 1024 + w * 256,
                     DM, 2048, 256, 2048, (tt >> 1) * 128, (tt & 1) * 128, 1.f);
    }
}

// --------------------------------------------------------------------------
// Launcher: ONE kernel.
// --------------------------------------------------------------------------
extern "C" void kernel_launch(void* const* d_in, const int* in_sizes, int n_in,
                              void* d_out, int out_size)
{
    const float* X    = (const float*)d_in[0];
    const float* Wq   = (const float*)d_in[1];
    const float* Wdkv = (const float*)d_in[2];
    const float* Wuk  = (const float*)d_in[3];
    const float* Wuv  = (const float*)d_in[4];
    const float* Wo   = (const float*)d_in[5];
    const float* wW   = (const float*)d_in[6];
    const float* wb   = (const float*)d_in[7];
    float* out = (float*)d_out;

    unsigned *qh, *kh, *vt;
    float *ckv, *ctx;
    cudaGetSymbolAddress((void**)&qh,  g_qh);
    cudaGetSymbolAddress((void**)&ckv, g_ckv);
    cudaGetSymbolAddress((void**)&kh,  g_kh);
    cudaGetSymbolAddress((void**)&vt,  g_vt);
    cudaGetSymbolAddress((void**)&ctx, g_ctx);

    const int smem = 23040 * (int)sizeof(unsigned);  // 92160 B
    cudaFuncSetAttribute(mega, cudaFuncAttributeMaxDynamicSharedMemorySize, smem);
    mega<<<NCTA, 256, smem>>>(X, Wq, Wdkv, Wuk, Wuv, Wo, wW, wb, out,
                              qh, ckv, kh, vt, ctx);
}

// round 15
// speedup vs baseline: 2.1377x; 1.3728x over previous
#include <cuda_runtime.h>
#include <math.h>

#define SEQ 2048
#define DM  1024
#define NH  16
#define HD  64
#define LAT 256
#define NCTA 148

// Scratch — device globals (no allocation allowed).
__device__ unsigned g_qh[SEQ * (DM / 2)];   // half2 col pairs, pre-scaled
__device__ float    g_ckv[SEQ * LAT];
__device__ unsigned g_kh[SEQ * (DM / 2)];   // half2 col pairs
__device__ unsigned g_vt[(SEQ / 2) * DM];   // half2 {V[2kp][d], V[2kp+1][d]}
__device__ float    g_ctx[SEQ * DM];

// Global software barrier state (zero-initialized).
__device__ unsigned g_cnt;
__device__ volatile unsigned g_phase;

// --------------------------------------------------------------------------
// helpers
// --------------------------------------------------------------------------
__device__ __forceinline__ float fex2(float x) {
    float y;
    asm("ex2.approx.f32 %0, %1;" : "=f"(y) : "f"(x));
    return y;
}
__device__ __forceinline__ unsigned packh2(float lo, float hi) {
    unsigned r;
    asm("cvt.rn.f16x2.f32 %0, %1, %2;" : "=r"(r) : "f"(hi), "f"(lo));
    return r;
}
__device__ __forceinline__ void mma_f16(float* c, const unsigned* a,
                                        unsigned b0, unsigned b1) {
    asm volatile(
        "mma.sync.aligned.m16n8k16.row.col.f32.f16.f16.f32 "
        "{%0,%1,%2,%3}, {%4,%5,%6,%7}, {%8,%9}, {%0,%1,%2,%3};"
        : "+f"(c[0]), "+f"(c[1]), "+f"(c[2]), "+f"(c[3])
        : "r"(a[0]), "r"(a[1]), "r"(a[2]), "r"(a[3]),
          "r"(b0), "r"(b1));
}
__device__ __forceinline__ void bar_g(int id) {
    asm volatile("bar.sync %0, %1;" :: "r"(id), "r"(128) : "memory");
}

// Grid-wide barrier: all 148 CTAs resident.
__device__ __forceinline__ void grid_bar(unsigned target) {
    __syncthreads();
    if (threadIdx.x == 0) {
        __threadfence();
        unsigned arr = atomicAdd(&g_cnt, 1u);
        if (arr == NCTA - 1) {
            atomicExch(&g_cnt, 0u);
            __threadfence();
            g_phase = target;
        } else {
            while (g_phase != target) { asm volatile("nanosleep.u32 64;"); }
            __threadfence();
        }
    }
    __syncthreads();
}

// --------------------------------------------------------------------------
// GEMM tile, fp16 m16n8k16: 256 threads, 128x128 tile, BK=32.
// A staged as packed half2 segments: As[m*36 + (p&3)*8 + (p>>2)], p=0..15.
// B staged k-pair-major half2:      Bs[kp*132 + n], kp=0..15.
// MODE 0: fp32 out (+bias). MODE 2: half2 col-pair pack (*oscale) -> uint* C.
// MODE 3: half2 pair-major rows (V transpose-pack) -> uint* C.
// --------------------------------------------------------------------------
#define AP2 36
#define BP2 132
template <int MODE>
__device__ void gemm_tile(unsigned* smem,
    const float* __restrict__ A, const float* __restrict__ B,
    const float* __restrict__ bias, float* __restrict__ C,
    int K, int lda, int ldb, int ldc, int m0, int n0, float oscale)
{
    unsigned* As = smem;                 // 128*36 = 4608 w
    unsigned* Bs = smem + 128 * AP2;     // 16*132 = 2112 w

    const int tid  = threadIdx.x;
    const int lane = tid & 31;
    const int warp = tid >> 5;
    const int g = lane >> 2;
    const int r = lane & 3;
    const int wm = warp & 3;
    const int wn = warp >> 2;

    float acc[2][8][4];
    #pragma unroll
    for (int i = 0; i < 2; i++)
        #pragma unroll
        for (int j = 0; j < 8; j++)
            #pragma unroll
            for (int t = 0; t < 4; t++) acc[i][j][t] = 0.f;

    for (int k0 = 0; k0 < K; k0 += 32) {
        // A tile 128x32 -> packed half2 (float4 loads, 2 packs each)
        #pragma unroll
        for (int e = 0; e < 4; e++) {
            int idx = e * 256 + tid;
            int m = idx >> 3, t = idx & 7;
            float4 a4 = *reinterpret_cast<const float4*>(
                &A[(long)(m0 + m) * lda + k0 + t * 4]);
            int p0 = 2 * t, p1 = 2 * t + 1;
            As[m * AP2 + (p0 & 3) * 8 + (p0 >> 2)] = packh2(a4.x, a4.y);
            As[m * AP2 + (p1 & 3) * 8 + (p1 >> 2)] = packh2(a4.z, a4.w);
        }
        // B tile 32x128 -> k-pair-major half2 (two row float4 loads, uint4 store)
        #pragma unroll
        for (int e = 0; e < 2; e++) {
            int idx = e * 256 + tid;
            int kp = idx >> 5, n = (idx & 31) * 4;
            float4 b0 = *reinterpret_cast<const float4*>(
                &B[(long)(k0 + 2 * kp) * ldb + n0 + n]);
            float4 b1 = *reinterpret_cast<const float4*>(
                &B[(long)(k0 + 2 * kp + 1) * ldb + n0 + n]);
            uint4 w;
            w.x = packh2(b0.x, b1.x);
            w.y = packh2(b0.y, b1.y);
            w.z = packh2(b0.z, b1.z);
            w.w = packh2(b0.w, b1.w);
            *reinterpret_cast<uint4*>(&Bs[kp * BP2 + n]) = w;
        }
        __syncthreads();

        // A fragments for both chunks: one uint4 per row (j=0..3 = pairs r,r+4,r+8,r+12)
        uint4 AL[2], AH[2];
        #pragma unroll
        for (int i = 0; i < 2; i++) {
            int row = wm * 32 + i * 16;
            AL[i] = *reinterpret_cast<const uint4*>(&As[(row + g)     * AP2 + r * 8]);
            AH[i] = *reinterpret_cast<const uint4*>(&As[(row + g + 8) * AP2 + r * 8]);
        }
        #pragma unroll
        for (int kt = 0; kt < 2; kt++) {
            unsigned a[2][4];
            a[0][0] = kt ? AL[0].z : AL[0].x;
            a[0][1] = kt ? AH[0].z : AH[0].x;
            a[0][2] = kt ? AL[0].w : AL[0].y;
            a[0][3] = kt ? AH[0].w : AH[0].y;
            a[1][0] = kt ? AL[1].z : AL[1].x;
            a[1][1] = kt ? AH[1].z : AH[1].x;
            a[1][2] = kt ? AL[1].w : AL[1].y;
            a[1][3] = kt ? AH[1].w : AH[1].y;
            #pragma unroll
            for (int j = 0; j < 8; j++) {
                int col = wn * 64 + j * 8;
                unsigned b0 = Bs[(kt * 8 + r)     * BP2 + col + g];
                unsigned b1 = Bs[(kt * 8 + r + 4) * BP2 + col + g];
                mma_f16(acc[0][j], a[0], b0, b1);
                mma_f16(acc[1][j], a[1], b0, b1);
            }
        }
        __syncthreads();
    }

    #pragma unroll
    for (int i = 0; i < 2; i++) {
        int row = m0 + wm * 32 + i * 16;
        #pragma unroll
        for (int j = 0; j < 8; j++) {
            int col = n0 + wn * 64 + j * 8 + 2 * r;
            float c00 = acc[i][j][0], c01 = acc[i][j][1];
            float c10 = acc[i][j][2], c11 = acc[i][j][3];
            if (MODE == 3) {
                float d00 = __shfl_down_sync(0xffffffffu, c00, 4);
                float d01 = __shfl_down_sync(0xffffffffu, c01, 4);
                float d10 = __shfl_down_sync(0xffffffffu, c10, 4);
                float d11 = __shfl_down_sync(0xffffffffu, c11, 4);
                if (!(g & 1)) {
                    unsigned* vt = (unsigned*)C;
                    int kp  = (row + g) >> 1;
                    int kp2 = (row + g + 8) >> 1;
                    uint2 v0 = make_uint2(packh2(c00, d00), packh2(c01, d01));
                    uint2 v1 = make_uint2(packh2(c10, d10), packh2(c11, d11));
                    *reinterpret_cast<uint2*>(&vt[(long)kp  * DM + col]) = v0;
                    *reinterpret_cast<uint2*>(&vt[(long)kp2 * DM + col]) = v1;
                }
            } else if (MODE == 2) {
                unsigned* ch = (unsigned*)C;
                int ldh = ldc >> 1;
                ch[(long)(row + g)     * ldh + (col >> 1)] =
                    packh2(c00 * oscale, c01 * oscale);
                ch[(long)(row + g + 8) * ldh + (col >> 1)] =
                    packh2(c10 * oscale, c11 * oscale);
            } else {
                float b0 = 0.f, b1 = 0.f;
                if (bias) { b0 = bias[col]; b1 = bias[col + 1]; }
                *reinterpret_cast<float2*>(&C[(long)(row + g) * ldc + col]) =
                    make_float2(c00 + b0, c01 + b1);
                *reinterpret_cast<float2*>(&C[(long)(row + g + 8) * ldc + col]) =
                    make_float2(c10 + b0, c11 + b1);
            }
        }
    }
}

// --------------------------------------------------------------------------
// Flash group — FULL fp16 path (proven R14): 4 warps, 128 queries,
// 32 rows/warp. Group smem: KB 3072 + VT 2304 + QB 4*1536 = 11520 w.
// --------------------------------------------------------------------------
__device__ void flash_group(unsigned* KB, int barid, int h, int i0,
    const unsigned* __restrict__ qh, const unsigned* __restrict__ kh,
    const unsigned* __restrict__ vt, float* __restrict__ ctx)
{
    unsigned* VT = KB + 3072;
    unsigned* QB = KB + 5376;

    const int tid  = threadIdx.x & 127;
    const int lane = tid & 31;
    const int warp = tid >> 5;
    const int g = lane >> 2;
    const int r = lane & 3;
    const int wbase = warp * 1536;

    #pragma unroll
    for (int e = 0; e < 8; e++) {
        int idx = e * 128 + tid;
        int row = idx >> 3, t = idx & 7;
        uint4 q4 = *reinterpret_cast<const uint4*>(
            &qh[(long)(i0 + row) * (DM / 2) + h * 32 + t * 4]);
        unsigned* p = &QB[(row >> 5) * 1536 + (row & 31) * 48 + t];
        p[0]  = q4.x;
        p[12] = q4.y;
        p[24] = q4.z;
        p[36] = q4.w;
    }
    bar_g(barid);

    unsigned qa[2][4][4];
    #pragma unroll
    for (int i = 0; i < 2; i++) {
        const uint4* lo4 = reinterpret_cast<const uint4*>(
            &QB[wbase + (i * 16 + g) * 48 + r * 12]);
        const uint4* hi4 = reinterpret_cast<const uint4*>(
            &QB[wbase + (i * 16 + g + 8) * 48 + r * 12]);
        uint4 L[2] = {lo4[0], lo4[1]};
        uint4 H[2] = {hi4[0], hi4[1]};
        const unsigned* lo = reinterpret_cast<const unsigned*>(L);
        const unsigned* hi = reinterpret_cast<const unsigned*>(H);
        #pragma unroll
        for (int kt = 0; kt < 4; kt++) {
            qa[i][kt][0] = lo[2 * kt];
            qa[i][kt][1] = hi[2 * kt];
            qa[i][kt][2] = lo[2 * kt + 1];
            qa[i][kt][3] = hi[2 * kt + 1];
        }
    }

    float lsum[2][2];
    lsum[0][0] = lsum[0][1] = lsum[1][0] = lsum[1][1] = 0.f;
    float o[2][8][4];
    #pragma unroll
    for (int i = 0; i < 2; i++)
        #pragma unroll
        for (int j = 0; j < 8; j++)
            #pragma unroll
            for (int t = 0; t < 4; t++) o[i][j][t] = 0.f;

    for (int j0 = 0; j0 < SEQ; j0 += 64) {
        #pragma unroll
        for (int e = 0; e < 4; e++) {
            int idx = e * 128 + tid;
            int key = idx >> 3, t = idx & 7;
            uint4 k4 = *reinterpret_cast<const uint4*>(
                &kh[(long)(j0 + key) * (DM / 2) + h * 32 + t * 4]);
            unsigned* p = &KB[key * 48 + t];
            p[0]  = k4.x;
            p[12] = k4.y;
            p[24] = k4.z;
            p[36] = k4.w;
        }
        #pragma unroll
        for (int e = 0; e < 4; e++) {
            int idx = e * 128 + tid;
            int kp = idx >> 4, dq = idx & 15;
            uint4 v4 = *reinterpret_cast<const uint4*>(
                &vt[(long)((j0 >> 1) + kp) * DM + h * HD + dq * 4]);
            *reinterpret_cast<uint4*>(&VT[kp * 72 + dq * 4]) = v4;
        }
        bar_g(barid);

        #pragma unroll
        for (int half = 0; half < 2; half++) {
            const int nb = half * 4;

            float s[2][4][4];
            #pragma unroll
            for (int nt = 0; nt < 4; nt++) {
                #pragma unroll
                for (int i = 0; i < 2; i++)
                    #pragma unroll
                    for (int t = 0; t < 4; t++) s[i][nt][t] = 0.f;
                const uint4* kp4 = reinterpret_cast<const uint4*>(
                    &KB[((nb + nt) * 8 + g) * 48 + r * 12]);
                uint4 W0 = kp4[0], W1 = kp4[1];
                unsigned w[8] = {W0.x, W0.y, W0.z, W0.w, W1.x, W1.y, W1.z, W1.w};
                #pragma unroll
                for (int kt = 0; kt < 4; kt++) {
                    mma_f16(s[0][nt], qa[0][kt], w[2 * kt], w[2 * kt + 1]);
                    mma_f16(s[1][nt], qa[1][kt], w[2 * kt], w[2 * kt + 1]);
                }
            }

            #pragma unroll
            for (int i = 0; i < 2; i++)
                #pragma unroll
                for (int nt = 0; nt < 4; nt++) {
                    s[i][nt][0] = fex2(s[i][nt][0]);
                    s[i][nt][1] = fex2(s[i][nt][1]);
                    s[i][nt][2] = fex2(s[i][nt][2]);
                    s[i][nt][3] = fex2(s[i][nt][3]);
                    lsum[i][0] += s[i][nt][0] + s[i][nt][1];
                    lsum[i][1] += s[i][nt][2] + s[i][nt][3];
                }

            unsigned pa[2][2][4];
            #pragma unroll
            for (int i = 0; i < 2; i++)
                #pragma unroll
                for (int kt2 = 0; kt2 < 2; kt2++) {
                    pa[i][kt2][0] = packh2(s[i][2 * kt2][0],     s[i][2 * kt2][1]);
                    pa[i][kt2][1] = packh2(s[i][2 * kt2][2],     s[i][2 * kt2][3]);
                    pa[i][kt2][2] = packh2(s[i][2 * kt2 + 1][0], s[i][2 * kt2 + 1][1]);
                    pa[i][kt2][3] = packh2(s[i][2 * kt2 + 1][2], s[i][2 * kt2 + 1][3]);
                }

            #pragma unroll
            for (int kt2 = 0; kt2 < 2; kt2++) {
                const int kpb = half * 16 + kt2 * 8;
                #pragma unroll
                for (int nt = 0; nt < 8; nt++) {
                    unsigned b0 = VT[(kpb + r)     * 72 + nt * 8 + g];
                    unsigned b1 = VT[(kpb + r + 4) * 72 + nt * 8 + g];
                    mma_f16(o[0][nt], pa[0][kt2], b0, b1);
                    mma_f16(o[1][nt], pa[1][kt2], b0, b1);
                }
            }
        }
        bar_g(barid);
    }

    const int qb = warp * 32;
    #pragma unroll
    for (int i = 0; i < 2; i++) {
        float l0 = lsum[i][0], l1 = lsum[i][1];
        l0 += __shfl_xor_sync(0xffffffffu, l0, 1);
        l0 += __shfl_xor_sync(0xffffffffu, l0, 2);
        l1 += __shfl_xor_sync(0xffffffffu, l1, 1);
        l1 += __shfl_xor_sync(0xffffffffu, l1, 2);
        float inv0 = 1.0f / l0, inv1 = 1.0f / l1;
        #pragma unroll
        for (int nt = 0; nt < 8; nt++) {
            int col = h * HD + nt * 8 + 2 * r;
            *reinterpret_cast<float2*>(
                &ctx[(long)(i0 + qb + i * 16 + g) * DM + col]) =
                make_float2(o[i][nt][0] * inv0, o[i][nt][1] * inv0);
            *reinterpret_cast<float2*>(
                &ctx[(long)(i0 + qb + i * 16 + g + 8) * DM + col]) =
                make_float2(o[i][nt][2] * inv1, o[i][nt][3] * inv1);
        }
    }
}

// --------------------------------------------------------------------------
// Persistent mega-kernel: 148 CTAs x 256 threads, software grid barriers.
// --------------------------------------------------------------------------
__global__ void __launch_bounds__(256, 1) mega(
    const float* __restrict__ X,  const float* __restrict__ Wq,
    const float* __restrict__ Wdkv, const float* __restrict__ Wuk,
    const float* __restrict__ Wuv, const float* __restrict__ Wo,
    const float* __restrict__ wW, const float* __restrict__ wb,
    float* __restrict__ out,
    unsigned* __restrict__ qh, float* __restrict__ ckv,
    unsigned* __restrict__ kh, unsigned* __restrict__ vt,
    float* __restrict__ ctx)
{
    extern __shared__ unsigned smem[];
    const unsigned ph0 = g_phase;
    const int c = blockIdx.x;
    const float QSCALE = 0.125f * 1.4426950408889634f;

    // Phase A: 32 ckv + 116 q
    if (c < 32) {
        gemm_tile<0>(smem, X, Wdkv, nullptr, ckv,
                     DM, DM, LAT, LAT, (c >> 1) * 128, (c & 1) * 128, 1.f);
    } else {
        int qi = c - 32;
        gemm_tile<2>(smem, X, Wq, nullptr, (float*)qh,
                     DM, DM, DM, DM, (qi >> 3) * 128, (qi & 7) * 128, QSCALE);
    }
    grid_bar(ph0 + 1);

    // Phase B: 128 k + 128 v + 12 leftover q
    for (int t = c; t < 268; t += NCTA) {
        if (t < 128) {
            gemm_tile<2>(smem, ckv, Wuk, nullptr, (float*)kh,
                         LAT, LAT, DM, DM, (t >> 3) * 128, (t & 7) * 128, 1.f);
        } else if (t < 256) {
            int tt = t - 128;
            gemm_tile<3>(smem, ckv, Wuv, nullptr, (float*)vt,
                         LAT, LAT, DM, DM, (tt >> 3) * 128, (tt & 7) * 128, 1.f);
        } else {
            int qi = 116 + (t - 256);
            gemm_tile<2>(smem, X, Wq, nullptr, (float*)qh,
                         DM, DM, DM, DM, (qi >> 3) * 128, (qi & 7) * 128, QSCALE);
        }
    }
    grid_bar(ph0 + 2);

    // Phase C: flash — two 4-warp groups per CTA, 256 (head, qtile) tasks
    {
        int group = threadIdx.x >> 7;
        int t = c * 2 + group;
        if (t < 256)
            flash_group(smem + group * 11520, 1 + group,
                        t >> 4, (t & 15) * 128, qh, kh, vt, ctx);
    }
    grid_bar(ph0 + 3);

    // Phase D: body
    if (c < 128)
        gemm_tile<0>(smem, ctx, Wo, nullptr, out,
                     DM, DM, DM, 2048, (c >> 3) * 128, (c & 7) * 128, 1.f);
    grid_bar(ph0 + 4);

    // Phase E: wheels
    if (c < 128) {
        int w = c >> 5, tt = c & 31;
        gemm_tile<0>(smem, out, wW + (long)w * DM * 256, wb + w * 256,
                     out + 1024 + w * 256,
                     DM, 2048, 256, 2048, (tt >> 1) * 128, (tt & 1) * 128, 1.f);
    }
}

// --------------------------------------------------------------------------
// Launcher: ONE kernel.
// --------------------------------------------------------------------------
extern "C" void kernel_launch(void* const* d_in, const int* in_sizes, int n_in,
                              void* d_out, int out_size)
{
    const float* X    = (const float*)d_in[0];
    const float* Wq   = (const float*)d_in[1];
    const float* Wdkv = (const float*)d_in[2];
    const float* Wuk  = (const float*)d_in[3];
    const float* Wuv  = (const float*)d_in[4];
    const float* Wo   = (const float*)d_in[5];
    const float* wW   = (const float*)d_in[6];
    const float* wb   = (const float*)d_in[7];
    float* out = (float*)d_out;

    unsigned *qh, *kh, *vt;
    float *ckv, *ctx;
    cudaGetSymbolAddress((void**)&qh,  g_qh);
    cudaGetSymbolAddress((void**)&ckv, g_ckv);
    cudaGetSymbolAddress((void**)&kh,  g_kh);
    cudaGetSymbolAddress((void**)&vt,  g_vt);
    cudaGetSymbolAddress((void**)&ctx, g_ctx);

    const int smem = 23040 * (int)sizeof(unsigned);  // 92160 B
    cudaFuncSetAttribute(mega, cudaFuncAttributeMaxDynamicSharedMemorySize, smem);
    mega<<<NCTA, 256, smem>>>(X, Wq, Wdkv, Wuk, Wuv, Wo, wW, wb, out,
                              qh, ckv, kh, vt, ctx);
}